// round 10
// baseline (speedup 1.0000x reference)
#include <cuda_runtime.h>

typedef unsigned int U32;
typedef unsigned short U16;

static __device__ __forceinline__ float mish_f(float x){
    // mish(x) = x * ((1+e^x)^2 - 1) / ((1+e^x)^2 + 1), division via
    // bit-hack reciprocal + 2 Newton iterations (FMA pipe, no MUFU.RCP).
    float e  = __expf(fminf(x, 30.0f));
    float u  = 1.0f + e;
    float u2 = u * u;
    float d  = u2 + 1.0f;
    float r  = __int_as_float(0x7EF311C2 - __float_as_int(d));
    r = r * (2.0f - d * r);
    r = r * (2.0f - d * r);
    return x * (u2 - 1.0f) * r;
}

// g_AB: [pred(3)][half(2)][row(2048)][col(256)]  (P = x@W1_top, Q = x@W1_bot)
__device__ float g_AB[6 * 2048 * 256];
// g_W2h: W2 in fp16, fragment order: [pred(3)][nhalf(2)][chunk(4)][8192 halves]
__device__ U16 g_W2h[3 * 65536];

static __device__ __forceinline__ U32 pack_h2(float lo, float hi){
    U32 r;
    asm("cvt.rn.f16x2.f32 %0, %1, %2;" : "=r"(r) : "f"(hi), "f"(lo));
    return r;
}

static __device__ __forceinline__ void cp16(U32 dst, const void* src){
    asm volatile("cp.async.cg.shared.global [%0], [%1], 16;"
                 :: "r"(dst), "l"(src) : "memory");
}

// ---------------------------------------------------------------------------
// w2frag_kernel: W2 -> fp16 fragment layout (N split into halves of 128).
// ---------------------------------------------------------------------------
__global__ __launch_bounds__(256) void w2frag_kernel(
    const float* __restrict__ W2a,
    const float* __restrict__ W2b,
    const float* __restrict__ W2c)
{
    int idx = blockIdx.x * 256 + threadIdx.x;   // 0 .. 196607
    int p = idx >> 16;
    int rem = idx & 65535;
    int k = rem >> 8, n = rem & 255;
    const float* W2 = (p == 0) ? W2a : (p == 1) ? W2b : W2c;
    float v = W2[k * 256 + n];
    U16 hv;
    asm("{ .reg .f16 t; cvt.rn.f16.f32 t, %1; mov.b16 %0, t; }" : "=h"(hv) : "f"(v));
    int c = k >> 6, kk = k & 63;
    int ks = kk >> 4, r = kk & 15;
    int hi = r >> 3, r8 = r & 7, tl = r8 >> 1, comp = r8 & 1;
    int nhalf = n >> 7, nl = n & 127;
    int nt = nl >> 3, np = nt >> 1, odd = nt & 1, g = nl & 7;
    int lane = g * 4 + tl;
    int halfidx = ((ks * 8 + np) * 32 + lane) * 8 + (odd * 2 + hi) * 2 + comp;
    g_W2h[((p * 2 + nhalf) * 4 + c) * 8192 + halfidx] = hv;
}

// ---------------------------------------------------------------------------
// ab_kernel: P = x @ W1[:128,:], Q = x @ W1[128:,:] for each of 3 predicates.
// ---------------------------------------------------------------------------
__global__ __launch_bounds__(256) void ab_kernel(
    const float* __restrict__ emb,
    const float* __restrict__ W1a,
    const float* __restrict__ W1b,
    const float* __restrict__ W1c)
{
    __shared__ float Xs[16][65];
    __shared__ float Ws[16][64];
    int z = blockIdx.z;
    int p = z >> 1, half = z & 1;
    const float* W = (p == 0 ? W1a : (p == 1 ? W1b : W1c)) + half * 128 * 256;
    int row0 = blockIdx.y * 64;
    int col0 = blockIdx.x * 64;
    int tid = threadIdx.x;
    int tr = tid >> 4, tc = tid & 15;
    float acc[4][4];
    #pragma unroll
    for (int r = 0; r < 4; r++)
        #pragma unroll
        for (int c = 0; c < 4; c++) acc[r][c] = 0.0f;

    for (int k0 = 0; k0 < 128; k0 += 16){
        int kx = tid & 15, rx = tid >> 4;
        #pragma unroll
        for (int pp = 0; pp < 4; pp++)
            Xs[kx][rx + pp*16] = emb[(row0 + rx + pp*16)*128 + k0 + kx];
        int cw = tid & 63, kw = tid >> 6;
        #pragma unroll
        for (int pp = 0; pp < 4; pp++)
            Ws[kw + pp*4][cw] = W[(k0 + kw + pp*4)*256 + col0 + cw];
        __syncthreads();
        #pragma unroll
        for (int k = 0; k < 16; k++){
            float a[4], bv[4];
            #pragma unroll
            for (int r = 0; r < 4; r++) a[r] = Xs[k][tr*4 + r];
            #pragma unroll
            for (int c = 0; c < 4; c++) bv[c] = Ws[k][tc*4 + c];
            #pragma unroll
            for (int r = 0; r < 4; r++)
                #pragma unroll
                for (int c = 0; c < 4; c++)
                    acc[r][c] = fmaf(a[r], bv[c], acc[r][c]);
        }
        __syncthreads();
    }
    float* out = g_AB + (size_t)z * 2048 * 256;
    #pragma unroll
    for (int r = 0; r < 4; r++){
        float4 v = make_float4(acc[r][0], acc[r][1], acc[r][2], acc[r][3]);
        *(float4*)&out[(row0 + tr*4 + r)*256 + col0 + tc*4] = v;
    }
}

// ---------------------------------------------------------------------------
// p0_kernel: arity-1 residual MLP.
// ---------------------------------------------------------------------------
__global__ __launch_bounds__(256) void p0_kernel(
    const float* __restrict__ emb,
    const float* __restrict__ W1,
    const float* __restrict__ b1,
    const float* __restrict__ W2,
    const float* __restrict__ b2,
    float* __restrict__ out)
{
    __shared__ float buf[128][65];
    __shared__ float wch[16][128];
    __shared__ float bias[128];
    int row0 = blockIdx.x * 64;
    int tid = threadIdx.x;
    int tr = tid >> 5, tc = tid & 31;

    for (int idx = tid; idx < 64*128; idx += 256){
        int k = idx & 127, r = idx >> 7;
        buf[k][r] = emb[(row0 + r)*128 + k];
    }
    if (tid < 128) bias[tid] = b1[tid];
    __syncthreads();

    float acc[8][4];
    #pragma unroll
    for (int r = 0; r < 8; r++)
        #pragma unroll
        for (int c = 0; c < 4; c++) acc[r][c] = 0.0f;

    for (int k0 = 0; k0 < 128; k0 += 16){
        #pragma unroll
        for (int pp = 0; pp < 8; pp++){
            int idx = tid + pp*256;
            int c = idx & 127, kk = idx >> 7;
            wch[kk][c] = W1[(k0 + kk)*128 + c];
        }
        __syncthreads();
        #pragma unroll
        for (int k = 0; k < 16; k++){
            float a[8], bv[4];
            #pragma unroll
            for (int r = 0; r < 8; r++) a[r] = buf[k0 + k][tr*8 + r];
            #pragma unroll
            for (int c = 0; c < 4; c++) bv[c] = wch[k][tc*4 + c];
            #pragma unroll
            for (int r = 0; r < 8; r++)
                #pragma unroll
                for (int c = 0; c < 4; c++)
                    acc[r][c] = fmaf(a[r], bv[c], acc[r][c]);
        }
        __syncthreads();
    }

    float hval[8][4];
    #pragma unroll
    for (int r = 0; r < 8; r++)
        #pragma unroll
        for (int c = 0; c < 4; c++)
            hval[r][c] = mish_f(acc[r][c] + bias[tc*4 + c]);
    __syncthreads();
    #pragma unroll
    for (int r = 0; r < 8; r++)
        #pragma unroll
        for (int c = 0; c < 4; c++)
            buf[tc*4 + c][tr*8 + r] = hval[r][c];
    if (tid < 128) bias[tid] = b2[tid];

    float acc2[8][4];
    #pragma unroll
    for (int r = 0; r < 8; r++)
        #pragma unroll
        for (int c = 0; c < 4; c++) acc2[r][c] = 0.0f;

    for (int k0 = 0; k0 < 128; k0 += 16){
        #pragma unroll
        for (int pp = 0; pp < 8; pp++){
            int idx = tid + pp*256;
            int c = idx & 127, kk = idx >> 7;
            wch[kk][c] = W2[(k0 + kk)*128 + c];
        }
        __syncthreads();
        #pragma unroll
        for (int k = 0; k < 16; k++){
            float a[8], bv[4];
            #pragma unroll
            for (int r = 0; r < 8; r++) a[r] = buf[k0 + k][tr*8 + r];
            #pragma unroll
            for (int c = 0; c < 4; c++) bv[c] = wch[k][tc*4 + c];
            #pragma unroll
            for (int r = 0; r < 8; r++)
                #pragma unroll
                for (int c = 0; c < 4; c++)
                    acc2[r][c] = fmaf(a[r], bv[c], acc2[r][c]);
        }
        __syncthreads();
    }

    #pragma unroll
    for (int r = 0; r < 8; r++){
        int row = row0 + tr*8 + r;
        float4 x = *(const float4*)&emb[row*128 + tc*4];
        float4 o = make_float4(x.x + acc2[r][0] + bias[tc*4+0],
                               x.y + acc2[r][1] + bias[tc*4+1],
                               x.z + acc2[r][2] + bias[tc*4+2],
                               x.w + acc2[r][3] + bias[tc*4+3]);
        *(float4*)&out[row*128 + tc*4] = o;
    }
}

// ---------------------------------------------------------------------------
// pair_mma_kernel (strip-persistent): arity-2 via fp16 mma.sync m16n8k16.
// CTA = (pred p, nhalf, strip of 8 ti). W2 (all 4 K-chunks, 64KB fp16) is
// loaded into smem ONCE per CTA and reused across the 8 tiles. Per tile:
// M=64 (j rows), N=128, K=256; produce A (mish fragments) per chunk, double
// buffered; consume against resident W2. Epilogue reads x_j residual with
// direct L2-hot LDGs (no smem staging).
// 256 threads, 8 warps (2M x 4N), warp tile 32x32, acc 32 regs/thread.
// SMEM: A0[0,8192) A1[8192,16384) W2[16384,81920) av[81920,82944)
//       xi[82944,83456) b2[83456,83968)  -> 84KB, 2 CTAs/SM.
// ---------------------------------------------------------------------------
#define PAIR_SMEM_BYTES 83968
#define STRIP 8

#define MMA_F16(d, a, b0v, b1v) \
    asm volatile("mma.sync.aligned.m16n8k16.row.col.f32.f16.f16.f32 " \
        "{%0,%1,%2,%3}, {%4,%5,%6,%7}, {%8,%9}, {%0,%1,%2,%3};" \
        : "+f"(d[0]), "+f"(d[1]), "+f"(d[2]), "+f"(d[3]) \
        : "r"((a).x), "r"((a).y), "r"((a).z), "r"((a).w), \
          "r"(b0v), "r"(b1v))

__global__ __launch_bounds__(256, 2) void pair_mma_kernel(
    const float* __restrict__ emb,
    const float* __restrict__ b1a, const float* __restrict__ b1b, const float* __restrict__ b1c,
    const float* __restrict__ b2a, const float* __restrict__ b2b, const float* __restrict__ b2c,
    float* __restrict__ outbase)
{
    extern __shared__ char smc[];
    float* av   = (float*)(smc + 81920);
    float* xi_s = (float*)(smc + 82944);
    float* b2_s = (float*)(smc + 83456);
    U32 smem32;
    asm("{ .reg .u64 t; cvta.to.shared.u64 t, %1; cvt.u32.u64 %0, t; }"
        : "=r"(smem32) : "l"(smc));

    int p = blockIdx.y;
    const float* b1 = (p == 0) ? b1a : (p == 1) ? b1b : b1c;
    const float* b2 = (p == 0) ? b2a : (p == 1) ? b2b : b2c;
    float* outp = outbase + (size_t)p * 33554432;

    int bx = blockIdx.x;
    int nhalf = bx & 1;
    int strip = bx >> 1;              // 0..255, covers ti = strip*8..+7
    const uint4* Wsrc = (const uint4*)g_W2h + (size_t)(p*2 + nhalf) * 4096;

    int t = threadIdx.x;
    int wid = t >> 5, lane = t & 31;
    int wm = wid & 1, wn = wid >> 1;
    int g = lane >> 2, tl = lane & 3;

    // one-time: stage b2 half; load full W2 (64KB) into resident smem
    if (t < 32){
        float4 bv = ((const float4*)(b2 + nhalf*128))[t];
        *(float4*)&b2_s[t*4] = bv;
    }
    {
        U32 Wa = smem32 + 16384;
        #pragma unroll
        for (int it = 0; it < 16; it++)
            cp16(Wa + (U32)(t + it*256) * 16u, Wsrc + t + it*256);
        asm volatile("cp.async.commit_group;" ::: "memory");
        asm volatile("cp.async.wait_group 0;" ::: "memory");
    }

    char* A0 = smc;
    char* A1 = smc + 8192;
    char* Wb = smc + 16384;           // chunk c at Wb + c*16384

    for (int s = 0; s < STRIP; s++){
        int ti = strip * STRIP + s;
        int b = ti >> 6;
        const float* Pi = g_AB + ((size_t)(p*2) * 2048 + (size_t)ti) * 256;
        const float* Q  = g_AB + ((size_t)(p*2 + 1) * 2048 + (size_t)(b*64)) * 256;
        const float* embB = emb + (size_t)(b*64) * 128;

        __syncthreads();              // prev tile fully consumed (av/A/xi free)
        av[t] = Pi[t] + b1[t];
        if (t < 32 && nhalf == 0){
            float4 v = ((const float4*)(emb + (size_t)ti * 128))[t];
            *(float4*)&xi_s[t*4] = v;
        }
        __syncthreads();

        // A (h) fragments: 2 uint4 per thread per chunk, exact mma layout
        auto produceA = [&](int c, char* Ab){
            #pragma unroll
            for (int e = 0; e < 2; e++){
                int idx = t + e*256;
                int ks = idx >> 7;
                int mt = (idx >> 5) & 3;
                int ln = idx & 31;
                int gg = ln >> 2, tll = ln & 3;
                int j = mt*16 + gg;
                int kb = c*64 + ks*16 + 2*tll;
                const float* qr0 = Q + (size_t)j * 256 + kb;
                const float* qr1 = qr0 + 8 * 256;
                float2 qa0 = *(const float2*)qr0;
                float2 qa1 = *(const float2*)(qr0 + 8);
                float2 qb0 = *(const float2*)qr1;
                float2 qb1 = *(const float2*)(qr1 + 8);
                float2 av0 = *(const float2*)(av + kb);
                float2 av1 = *(const float2*)(av + kb + 8);
                U32 a0 = pack_h2(mish_f(av0.x + qa0.x), mish_f(av0.y + qa0.y));
                U32 a1 = pack_h2(mish_f(av0.x + qb0.x), mish_f(av0.y + qb0.y));
                U32 a2 = pack_h2(mish_f(av1.x + qa1.x), mish_f(av1.y + qa1.y));
                U32 a3 = pack_h2(mish_f(av1.x + qb1.x), mish_f(av1.y + qb1.y));
                *(uint4*)(Ab + (((ks*4 + mt)*32 + ln) << 4)) = make_uint4(a0,a1,a2,a3);
            }
        };

        float acc[2][4][4];
        #pragma unroll
        for (int mf = 0; mf < 2; mf++)
            #pragma unroll
            for (int nf = 0; nf < 4; nf++)
                #pragma unroll
                for (int u = 0; u < 4; u++) acc[mf][nf][u] = 0.0f;

        auto consume = [&](char* Ab, int c){
            char* Bb = Wb + c*16384;
            #pragma unroll
            for (int ks = 0; ks < 4; ks++){
                uint4 aA = *(uint4*)(Ab + (((ks*4 + wm*2    )*32 + lane) << 4));
                uint4 aB = *(uint4*)(Ab + (((ks*4 + wm*2 + 1)*32 + lane) << 4));
                #pragma unroll
                for (int npp = 0; npp < 2; npp++){
                    uint4 v = *(uint4*)(Bb + (((ks*8 + wn*2 + npp)*32 + lane) << 4));
                    MMA_F16(acc[0][2*npp    ], aA, v.x, v.y);
                    MMA_F16(acc[1][2*npp    ], aB, v.x, v.y);
                    MMA_F16(acc[0][2*npp + 1], aA, v.z, v.w);
                    MMA_F16(acc[1][2*npp + 1], aB, v.z, v.w);
                }
            }
        };

        produceA(0, A0);
        __syncthreads();
        produceA(1, A1); consume(A0, 0);
        __syncthreads();
        produceA(2, A0); consume(A1, 1);
        __syncthreads();
        produceA(3, A1); consume(A0, 2);
        __syncthreads();
        consume(A1, 3);

        // ---- epilogue: residual + bias, direct LDG for x_j ----
        size_t rowbase = (size_t)ti * 64;
        int colbase = nhalf * 128;

        #pragma unroll
        for (int mf = 0; mf < 2; mf++){
            int jr0 = wm*32 + mf*16 + g;
            int jr1 = jr0 + 8;
            float* o0 = outp + (rowbase + jr0) * 256 + colbase;
            float* o1 = outp + (rowbase + jr1) * 256 + colbase;
            #pragma unroll
            for (int nf = 0; nf < 4; nf++){
                int col = wn*32 + nf*8 + 2*tl;
                float add00, add01, add10, add11;
                if (nhalf == 0){
                    float x0 = xi_s[col], x1 = xi_s[col + 1];
                    add00 = x0; add01 = x1; add10 = x0; add11 = x1;
                } else {
                    float2 va = __ldg((const float2*)(embB + (size_t)jr0*128 + col));
                    float2 vb = __ldg((const float2*)(embB + (size_t)jr1*128 + col));
                    add00 = va.x; add01 = va.y;
                    add10 = vb.x; add11 = vb.y;
                }
                float bb0 = b2_s[col], bb1 = b2_s[col + 1];
                float2 v0 = make_float2(acc[mf][nf][0] + add00 + bb0,
                                        acc[mf][nf][1] + add01 + bb1);
                float2 v1 = make_float2(acc[mf][nf][2] + add10 + bb0,
                                        acc[mf][nf][3] + add11 + bb1);
                *(float2*)&o0[col] = v0;
                *(float2*)&o1[col] = v1;
            }
        }
    }
}

// ---------------------------------------------------------------------------
extern "C" void kernel_launch(void* const* d_in, const int* in_sizes, int n_in,
                              void* d_out, int out_size)
{
    (void)in_sizes; (void)n_in; (void)out_size;
    const float* emb  = (const float*)d_in[0];
    const float* W1_0 = (const float*)d_in[2];
    const float* b1_0 = (const float*)d_in[3];
    const float* W2_0 = (const float*)d_in[4];
    const float* b2_0 = (const float*)d_in[5];
    const float* W1_1 = (const float*)d_in[6];
    const float* b1_1 = (const float*)d_in[7];
    const float* W2_1 = (const float*)d_in[8];
    const float* b2_1 = (const float*)d_in[9];
    const float* W1_2 = (const float*)d_in[10];
    const float* b1_2 = (const float*)d_in[11];
    const float* W2_2 = (const float*)d_in[12];
    const float* b2_2 = (const float*)d_in[13];
    const float* W1_3 = (const float*)d_in[14];
    const float* b1_3 = (const float*)d_in[15];
    const float* W2_3 = (const float*)d_in[16];
    const float* b2_3 = (const float*)d_in[17];
    float* out = (float*)d_out;

    static int smem_set = 0;
    if (!smem_set){
        cudaFuncSetAttribute(pair_mma_kernel,
                             cudaFuncAttributeMaxDynamicSharedMemorySize,
                             PAIR_SMEM_BYTES);
        smem_set = 1;
    }

    w2frag_kernel<<<768, 256>>>(W2_1, W2_2, W2_3);
    ab_kernel<<<dim3(4, 32, 6), 256>>>(emb, W1_1, W1_2, W1_3);
    p0_kernel<<<32, 256>>>(emb, W1_0, b1_0, W2_0, b2_0, out);
    pair_mma_kernel<<<dim3(512, 3), 256, PAIR_SMEM_BYTES>>>(
        emb,
        b1_1, b1_2, b1_3,
        b2_1, b2_2, b2_3,
        out + 262144);
}

// round 11
// speedup vs baseline: 1.0830x; 1.0830x over previous
#include <cuda_runtime.h>

typedef unsigned int U32;
typedef unsigned short U16;

static __device__ __forceinline__ float mish_f(float x){
    // mish(x) = x * ((1+e^x)^2 - 1) / ((1+e^x)^2 + 1), division via
    // bit-hack reciprocal + 2 Newton iterations (FMA pipe, no MUFU.RCP).
    float e  = __expf(fminf(x, 30.0f));
    float u  = 1.0f + e;
    float u2 = u * u;
    float d  = u2 + 1.0f;
    float r  = __int_as_float(0x7EF311C2 - __float_as_int(d));
    r = r * (2.0f - d * r);
    r = r * (2.0f - d * r);
    return x * (u2 - 1.0f) * r;
}

// g_AB: [pred(3)][half(2)][row(2048)][col(256)]  (P = x@W1_top, Q = x@W1_bot)
__device__ float g_AB[6 * 2048 * 256];
// g_W2h: W2 in fp16, fragment order: [pred(3)][nhalf(2)][chunk(4)][8192 halves]
__device__ U16 g_W2h[3 * 65536];

static __device__ __forceinline__ U32 pack_h2(float lo, float hi){
    U32 r;
    asm("cvt.rn.f16x2.f32 %0, %1, %2;" : "=r"(r) : "f"(hi), "f"(lo));
    return r;
}

static __device__ __forceinline__ void cp16(U32 dst, const void* src){
    asm volatile("cp.async.cg.shared.global [%0], [%1], 16;"
                 :: "r"(dst), "l"(src) : "memory");
}

// ---------------------------------------------------------------------------
// w2frag_kernel: W2 -> fp16 fragment layout (N split into halves of 128).
// ---------------------------------------------------------------------------
__global__ __launch_bounds__(256) void w2frag_kernel(
    const float* __restrict__ W2a,
    const float* __restrict__ W2b,
    const float* __restrict__ W2c)
{
    int idx = blockIdx.x * 256 + threadIdx.x;   // 0 .. 196607
    int p = idx >> 16;
    int rem = idx & 65535;
    int k = rem >> 8, n = rem & 255;
    const float* W2 = (p == 0) ? W2a : (p == 1) ? W2b : W2c;
    float v = W2[k * 256 + n];
    U16 hv;
    asm("{ .reg .f16 t; cvt.rn.f16.f32 t, %1; mov.b16 %0, t; }" : "=h"(hv) : "f"(v));
    int c = k >> 6, kk = k & 63;
    int ks = kk >> 4, r = kk & 15;
    int hi = r >> 3, r8 = r & 7, tl = r8 >> 1, comp = r8 & 1;
    int nhalf = n >> 7, nl = n & 127;
    int nt = nl >> 3, np = nt >> 1, odd = nt & 1, g = nl & 7;
    int lane = g * 4 + tl;
    int halfidx = ((ks * 8 + np) * 32 + lane) * 8 + (odd * 2 + hi) * 2 + comp;
    g_W2h[((p * 2 + nhalf) * 4 + c) * 8192 + halfidx] = hv;
}

// ---------------------------------------------------------------------------
// ab_kernel: P = x @ W1[:128,:], Q = x @ W1[128:,:] for each of 3 predicates.
// ---------------------------------------------------------------------------
__global__ __launch_bounds__(256) void ab_kernel(
    const float* __restrict__ emb,
    const float* __restrict__ W1a,
    const float* __restrict__ W1b,
    const float* __restrict__ W1c)
{
    __shared__ float Xs[16][65];
    __shared__ float Ws[16][64];
    int z = blockIdx.z;
    int p = z >> 1, half = z & 1;
    const float* W = (p == 0 ? W1a : (p == 1 ? W1b : W1c)) + half * 128 * 256;
    int row0 = blockIdx.y * 64;
    int col0 = blockIdx.x * 64;
    int tid = threadIdx.x;
    int tr = tid >> 4, tc = tid & 15;
    float acc[4][4];
    #pragma unroll
    for (int r = 0; r < 4; r++)
        #pragma unroll
        for (int c = 0; c < 4; c++) acc[r][c] = 0.0f;

    for (int k0 = 0; k0 < 128; k0 += 16){
        int kx = tid & 15, rx = tid >> 4;
        #pragma unroll
        for (int pp = 0; pp < 4; pp++)
            Xs[kx][rx + pp*16] = emb[(row0 + rx + pp*16)*128 + k0 + kx];
        int cw = tid & 63, kw = tid >> 6;
        #pragma unroll
        for (int pp = 0; pp < 4; pp++)
            Ws[kw + pp*4][cw] = W[(k0 + kw + pp*4)*256 + col0 + cw];
        __syncthreads();
        #pragma unroll
        for (int k = 0; k < 16; k++){
            float a[4], bv[4];
            #pragma unroll
            for (int r = 0; r < 4; r++) a[r] = Xs[k][tr*4 + r];
            #pragma unroll
            for (int c = 0; c < 4; c++) bv[c] = Ws[k][tc*4 + c];
            #pragma unroll
            for (int r = 0; r < 4; r++)
                #pragma unroll
                for (int c = 0; c < 4; c++)
                    acc[r][c] = fmaf(a[r], bv[c], acc[r][c]);
        }
        __syncthreads();
    }
    float* out = g_AB + (size_t)z * 2048 * 256;
    #pragma unroll
    for (int r = 0; r < 4; r++){
        float4 v = make_float4(acc[r][0], acc[r][1], acc[r][2], acc[r][3]);
        *(float4*)&out[(row0 + tr*4 + r)*256 + col0 + tc*4] = v;
    }
}

// ---------------------------------------------------------------------------
// p0_kernel: arity-1 residual MLP.
// ---------------------------------------------------------------------------
__global__ __launch_bounds__(256) void p0_kernel(
    const float* __restrict__ emb,
    const float* __restrict__ W1,
    const float* __restrict__ b1,
    const float* __restrict__ W2,
    const float* __restrict__ b2,
    float* __restrict__ out)
{
    __shared__ float buf[128][65];
    __shared__ float wch[16][128];
    __shared__ float bias[128];
    int row0 = blockIdx.x * 64;
    int tid = threadIdx.x;
    int tr = tid >> 5, tc = tid & 31;

    for (int idx = tid; idx < 64*128; idx += 256){
        int k = idx & 127, r = idx >> 7;
        buf[k][r] = emb[(row0 + r)*128 + k];
    }
    if (tid < 128) bias[tid] = b1[tid];
    __syncthreads();

    float acc[8][4];
    #pragma unroll
    for (int r = 0; r < 8; r++)
        #pragma unroll
        for (int c = 0; c < 4; c++) acc[r][c] = 0.0f;

    for (int k0 = 0; k0 < 128; k0 += 16){
        #pragma unroll
        for (int pp = 0; pp < 8; pp++){
            int idx = tid + pp*256;
            int c = idx & 127, kk = idx >> 7;
            wch[kk][c] = W1[(k0 + kk)*128 + c];
        }
        __syncthreads();
        #pragma unroll
        for (int k = 0; k < 16; k++){
            float a[8], bv[4];
            #pragma unroll
            for (int r = 0; r < 8; r++) a[r] = buf[k0 + k][tr*8 + r];
            #pragma unroll
            for (int c = 0; c < 4; c++) bv[c] = wch[k][tc*4 + c];
            #pragma unroll
            for (int r = 0; r < 8; r++)
                #pragma unroll
                for (int c = 0; c < 4; c++)
                    acc[r][c] = fmaf(a[r], bv[c], acc[r][c]);
        }
        __syncthreads();
    }

    float hval[8][4];
    #pragma unroll
    for (int r = 0; r < 8; r++)
        #pragma unroll
        for (int c = 0; c < 4; c++)
            hval[r][c] = mish_f(acc[r][c] + bias[tc*4 + c]);
    __syncthreads();
    #pragma unroll
    for (int r = 0; r < 8; r++)
        #pragma unroll
        for (int c = 0; c < 4; c++)
            buf[tc*4 + c][tr*8 + r] = hval[r][c];
    if (tid < 128) bias[tid] = b2[tid];

    float acc2[8][4];
    #pragma unroll
    for (int r = 0; r < 8; r++)
        #pragma unroll
        for (int c = 0; c < 4; c++) acc2[r][c] = 0.0f;

    for (int k0 = 0; k0 < 128; k0 += 16){
        #pragma unroll
        for (int pp = 0; pp < 8; pp++){
            int idx = tid + pp*256;
            int c = idx & 127, kk = idx >> 7;
            wch[kk][c] = W2[(k0 + kk)*128 + c];
        }
        __syncthreads();
        #pragma unroll
        for (int k = 0; k < 16; k++){
            float a[8], bv[4];
            #pragma unroll
            for (int r = 0; r < 8; r++) a[r] = buf[k0 + k][tr*8 + r];
            #pragma unroll
            for (int c = 0; c < 4; c++) bv[c] = wch[k][tc*4 + c];
            #pragma unroll
            for (int r = 0; r < 8; r++)
                #pragma unroll
                for (int c = 0; c < 4; c++)
                    acc2[r][c] = fmaf(a[r], bv[c], acc2[r][c]);
        }
        __syncthreads();
    }

    #pragma unroll
    for (int r = 0; r < 8; r++){
        int row = row0 + tr*8 + r;
        float4 x = *(const float4*)&emb[row*128 + tc*4];
        float4 o = make_float4(x.x + acc2[r][0] + bias[tc*4+0],
                               x.y + acc2[r][1] + bias[tc*4+1],
                               x.z + acc2[r][2] + bias[tc*4+2],
                               x.w + acc2[r][3] + bias[tc*4+3]);
        *(float4*)&out[row*128 + tc*4] = o;
    }
}

// ---------------------------------------------------------------------------
// pair_mma_kernel: arity-2 via fp16 mma.sync (m16n8k16, f32 acc).
// Block = (pred p, ti, N-half): 256 threads, 8 warps (2M x 4N), warp tile
// 32x32. M=64 (j rows), N=128, K=256 in 4 chunks of 64.
// A path: coalesced Q LDG (thread t owns row t>>2, 16 consecutive k) ->
// mish -> fp16 row-major smem with XOR swizzle -> ldmatrix.m8n8.x4.
// B path: prelaid fragments via cp.async (unchanged from R7).
// __launch_bounds__(256,3): 85-reg cap -> 3 CTAs/SM.
// SMEM bytes: A0[0,8192) A1[8192,16384) B0[16384,32768) B1[32768,49152)
//             av[49152,50176) xi[50176,50688) b2[50688,51200)
// Epilogue (nhalf=1): xj[64][132] floats overlaid at offset 0.
// ---------------------------------------------------------------------------
#define PAIR_SMEM_BYTES 51200

#define MMA_F16(d, a, b0v, b1v) \
    asm volatile("mma.sync.aligned.m16n8k16.row.col.f32.f16.f16.f32 " \
        "{%0,%1,%2,%3}, {%4,%5,%6,%7}, {%8,%9}, {%0,%1,%2,%3};" \
        : "+f"(d[0]), "+f"(d[1]), "+f"(d[2]), "+f"(d[3]) \
        : "r"((a).x), "r"((a).y), "r"((a).z), "r"((a).w), \
          "r"(b0v), "r"(b1v))

#define LDMATRIX_X4(v, addr) \
    asm volatile("ldmatrix.sync.aligned.m8n8.x4.shared.b16 {%0,%1,%2,%3}, [%4];" \
        : "=r"((v).x), "=r"((v).y), "=r"((v).z), "=r"((v).w) : "r"(addr))

__global__ __launch_bounds__(256, 3) void pair_mma_kernel(
    const float* __restrict__ emb,
    const float* __restrict__ b1a, const float* __restrict__ b1b, const float* __restrict__ b1c,
    const float* __restrict__ b2a, const float* __restrict__ b2b, const float* __restrict__ b2c,
    float* __restrict__ outbase)
{
    extern __shared__ char smc[];
    float* sm   = (float*)smc;
    float* av   = (float*)(smc + 49152);
    float* xi_s = (float*)(smc + 50176);
    float* b2_s = (float*)(smc + 50688);
    U32 smem32;
    asm("{ .reg .u64 t; cvta.to.shared.u64 t, %1; cvt.u32.u64 %0, t; }"
        : "=r"(smem32) : "l"(smc));

    int p = blockIdx.y;
    const float* b1 = (p == 0) ? b1a : (p == 1) ? b1b : b1c;
    const float* b2 = (p == 0) ? b2a : (p == 1) ? b2b : b2c;
    float* outp = outbase + (size_t)p * 33554432;

    int bx = blockIdx.x;
    int nhalf = bx & 1;
    int ti = bx >> 1;                 // 0..2047 = b*64 + i
    int b = ti >> 6;
    const float* Pi = g_AB + ((size_t)(p*2) * 2048 + (size_t)ti) * 256;
    const float* Q  = g_AB + ((size_t)(p*2 + 1) * 2048 + (size_t)(b*64)) * 256;
    const uint4* Wsrc = (const uint4*)g_W2h + (size_t)(p*2 + nhalf) * 4096;

    int t = threadIdx.x;
    int wid = t >> 5, lane = t & 31;
    int wm = wid & 1, wn = wid >> 1;
    int g = lane >> 2, tl = lane & 3;

    // av[k] = P[i][k] + b1[k]; stage xi (nhalf=0) and b2 half
    av[t] = Pi[t] + b1[t];
    if (t < 32){
        if (nhalf == 0){
            float4 v = ((const float4*)(emb + (size_t)ti * 128))[t];
            *(float4*)&xi_s[t*4] = v;
        }
        float4 bv = ((const float4*)(b2 + nhalf*128))[t];
        *(float4*)&b2_s[t*4] = bv;
    }
    __syncthreads();

    // W2 chunk async copy: 16KB = 1024 uint4, 4 per thread
    auto produceW = [&](int c, U32 Bs32){
        const uint4* src = Wsrc + c * 1024 + t;
        #pragma unroll
        for (int it = 0; it < 4; it++)
            cp16(Bs32 + (U32)(t + it*256) * 16u, src + it*256);
        asm volatile("cp.async.commit_group;" ::: "memory");
    };

    // A producer: thread t -> row j = t>>2, 16 consecutive k (sub = t&3).
    // Coalesced Q LDG.128 x4, broadcast av LDS, mish, pack, 2 swizzled STS.128.
    int pj  = t >> 2;
    int psub = t & 3;
    const float* qrow = Q + (size_t)pj * 256 + psub * 16;
    auto produceA = [&](int c, char* Ab){
        const float4* qp = (const float4*)(qrow + c*64);
        const float4* ap = (const float4*)(av + c*64 + psub*16);
        U32 h[8];
        #pragma unroll
        for (int i = 0; i < 4; i++){
            float4 q = qp[i];
            float4 a = ap[i];
            h[2*i]   = pack_h2(mish_f(a.x + q.x), mish_f(a.y + q.y));
            h[2*i+1] = pack_h2(mish_f(a.z + q.z), mish_f(a.w + q.w));
        }
        int s0 = psub * 2, rx = pj & 7;
        *(uint4*)(Ab + pj*128 + ((s0    ^ rx) << 4)) = make_uint4(h[0],h[1],h[2],h[3]);
        *(uint4*)(Ab + pj*128 + (((s0+1)^ rx) << 4)) = make_uint4(h[4],h[5],h[6],h[7]);
    };

    float acc[2][4][4];
    #pragma unroll
    for (int mf = 0; mf < 2; mf++)
        #pragma unroll
        for (int nf = 0; nf < 4; nf++)
            #pragma unroll
            for (int u = 0; u < 4; u++) acc[mf][nf][u] = 0.0f;

    // ldmatrix lane address components (m8n8.x4 -> m16n8k16 A order)
    int mi = lane >> 3, lr = lane & 7;
    int rowoff = (mi & 1) * 8 + lr;   // within 16-row tile
    int khi = mi >> 1;                // 0: k 0-7, 1: k 8-15
    int rsw = rowoff & 7;

    auto consume = [&](U32 Aa, char* Bb){
        U32 base0 = Aa + (U32)((wm*32 + rowoff) * 128);
        #pragma unroll
        for (int ks = 0; ks < 4; ks++){
            U32 ad = base0 + (U32)((((ks*2 + khi) ^ rsw) << 4));
            uint4 aA, aB;
            LDMATRIX_X4(aA, ad);
            LDMATRIX_X4(aB, ad + 2048);      // +16 rows
            #pragma unroll
            for (int npp = 0; npp < 2; npp++){
                uint4 v = *(uint4*)(Bb + (((ks*8 + wn*2 + npp)*32 + lane) << 4));
                MMA_F16(acc[0][2*npp    ], aA, v.x, v.y);
                MMA_F16(acc[1][2*npp    ], aB, v.x, v.y);
                MMA_F16(acc[0][2*npp + 1], aA, v.z, v.w);
                MMA_F16(acc[1][2*npp + 1], aB, v.z, v.w);
            }
        }
    };

    char* A0 = smc;          char* A1 = smc + 8192;
    char* B0 = smc + 16384;  char* B1 = smc + 32768;
    U32 A0a = smem32,         A1a = smem32 + 8192;
    U32 B0a = smem32 + 16384, B1a = smem32 + 32768;

    produceW(0, B0a); produceA(0, A0);
    asm volatile("cp.async.wait_group 0;" ::: "memory");
    __syncthreads();
    produceW(1, B1a); produceA(1, A1); consume(A0a, B0);
    asm volatile("cp.async.wait_group 0;" ::: "memory");
    __syncthreads();
    produceW(2, B0a); produceA(2, A0); consume(A1a, B1);
    asm volatile("cp.async.wait_group 0;" ::: "memory");
    __syncthreads();
    produceW(3, B1a); produceA(3, A1); consume(A0a, B0);
    asm volatile("cp.async.wait_group 0;" ::: "memory");
    __syncthreads();
    consume(A1a, B1);

    // ---- epilogue ----
    float* xj_s = sm;                 // [64][132] (nhalf=1 only), 33792 B fits
    if (nhalf == 1){
        __syncthreads();
        const float* embB = emb + (size_t)(b*64) * 128;
        #pragma unroll
        for (int it = 0; it < 8; it++){
            int idx = t + it*256;
            int jr = idx >> 5, c4 = idx & 31;
            float4 v = ((const float4*)(embB + (size_t)jr*128))[c4];
            *(float4*)&xj_s[jr*132 + c4*4] = v;
        }
    }
    __syncthreads();

    size_t rowbase = (size_t)ti * 64;
    int colbase = nhalf * 128;

    #pragma unroll
    for (int mf = 0; mf < 2; mf++){
        int jr0 = wm*32 + mf*16 + g;
        int jr1 = jr0 + 8;
        float* o0 = outp + (rowbase + jr0) * 256 + colbase;
        float* o1 = outp + (rowbase + jr1) * 256 + colbase;
        #pragma unroll
        for (int nf = 0; nf < 4; nf++){
            int col = wn*32 + nf*8 + 2*tl;
            float add00, add01, add10, add11;
            if (nhalf == 0){
                float x0 = xi_s[col], x1 = xi_s[col + 1];
                add00 = x0; add01 = x1; add10 = x0; add11 = x1;
            } else {
                add00 = xj_s[jr0*132 + col];
                add01 = xj_s[jr0*132 + col + 1];
                add10 = xj_s[jr1*132 + col];
                add11 = xj_s[jr1*132 + col + 1];
            }
            float bb0 = b2_s[col], bb1 = b2_s[col + 1];
            float2 v0 = make_float2(acc[mf][nf][0] + add00 + bb0,
                                    acc[mf][nf][1] + add01 + bb1);
            float2 v1 = make_float2(acc[mf][nf][2] + add10 + bb0,
                                    acc[mf][nf][3] + add11 + bb1);
            *(float2*)&o0[col] = v0;
            *(float2*)&o1[col] = v1;
        }
    }
}

// ---------------------------------------------------------------------------
extern "C" void kernel_launch(void* const* d_in, const int* in_sizes, int n_in,
                              void* d_out, int out_size)
{
    (void)in_sizes; (void)n_in; (void)out_size;
    const float* emb  = (const float*)d_in[0];
    const float* W1_0 = (const float*)d_in[2];
    const float* b1_0 = (const float*)d_in[3];
    const float* W2_0 = (const float*)d_in[4];
    const float* b2_0 = (const float*)d_in[5];
    const float* W1_1 = (const float*)d_in[6];
    const float* b1_1 = (const float*)d_in[7];
    const float* W2_1 = (const float*)d_in[8];
    const float* b2_1 = (const float*)d_in[9];
    const float* W1_2 = (const float*)d_in[10];
    const float* b1_2 = (const float*)d_in[11];
    const float* W2_2 = (const float*)d_in[12];
    const float* b2_2 = (const float*)d_in[13];
    const float* W1_3 = (const float*)d_in[14];
    const float* b1_3 = (const float*)d_in[15];
    const float* W2_3 = (const float*)d_in[16];
    const float* b2_3 = (const float*)d_in[17];
    float* out = (float*)d_out;

    static int smem_set = 0;
    if (!smem_set){
        cudaFuncSetAttribute(pair_mma_kernel,
                             cudaFuncAttributeMaxDynamicSharedMemorySize,
                             PAIR_SMEM_BYTES);
        smem_set = 1;
    }

    w2frag_kernel<<<768, 256>>>(W2_1, W2_2, W2_3);
    ab_kernel<<<dim3(4, 32, 6), 256>>>(emb, W1_1, W1_2, W1_3);
    p0_kernel<<<32, 256>>>(emb, W1_0, b1_0, W2_0, b2_0, out);
    pair_mma_kernel<<<dim3(4096, 3), 256, PAIR_SMEM_BYTES>>>(
        emb,
        b1_1, b1_2, b1_3,
        b2_1, b2_2, b2_3,
        out + 262144);
}

// round 12
// speedup vs baseline: 1.3340x; 1.2318x over previous
#include <cuda_runtime.h>

typedef unsigned int U32;
typedef unsigned short U16;

static __device__ __forceinline__ float mish_f(float x){
    // mish(x) = x * ((1+e^x)^2 - 1) / ((1+e^x)^2 + 1), division via
    // bit-hack reciprocal + 2 Newton iterations (FMA pipe, no MUFU.RCP).
    float e  = __expf(fminf(x, 30.0f));
    float u  = 1.0f + e;
    float u2 = u * u;
    float d  = u2 + 1.0f;
    float r  = __int_as_float(0x7EF311C2 - __float_as_int(d));
    r = r * (2.0f - d * r);
    r = r * (2.0f - d * r);
    return x * (u2 - 1.0f) * r;
}

// g_AB: [pred(3)][half(2)][row(2048)][col(256)]  (P = x@W1_top, Q = x@W1_bot)
__device__ float g_AB[6 * 2048 * 256];
// g_W2h: W2 in fp16, fragment order: [pred(3)][nhalf(2)][chunk(4)][8192 halves]
__device__ U16 g_W2h[3 * 65536];

static __device__ __forceinline__ U32 pack_h2(float lo, float hi){
    U32 r;
    asm("cvt.rn.f16x2.f32 %0, %1, %2;" : "=r"(r) : "f"(hi), "f"(lo));
    return r;
}

static __device__ __forceinline__ void cp16(U32 dst, const void* src){
    asm volatile("cp.async.cg.shared.global [%0], [%1], 16;"
                 :: "r"(dst), "l"(src) : "memory");
}

// ---------------------------------------------------------------------------
// w2frag_kernel: W2 -> fp16 fragment layout (N split into halves of 128).
// ---------------------------------------------------------------------------
__global__ __launch_bounds__(256) void w2frag_kernel(
    const float* __restrict__ W2a,
    const float* __restrict__ W2b,
    const float* __restrict__ W2c)
{
    int idx = blockIdx.x * 256 + threadIdx.x;   // 0 .. 196607
    int p = idx >> 16;
    int rem = idx & 65535;
    int k = rem >> 8, n = rem & 255;
    const float* W2 = (p == 0) ? W2a : (p == 1) ? W2b : W2c;
    float v = W2[k * 256 + n];
    U16 hv;
    asm("{ .reg .f16 t; cvt.rn.f16.f32 t, %1; mov.b16 %0, t; }" : "=h"(hv) : "f"(v));
    int c = k >> 6, kk = k & 63;
    int ks = kk >> 4, r = kk & 15;
    int hi = r >> 3, r8 = r & 7, tl = r8 >> 1, comp = r8 & 1;
    int nhalf = n >> 7, nl = n & 127;
    int nt = nl >> 3, np = nt >> 1, odd = nt & 1, g = nl & 7;
    int lane = g * 4 + tl;
    int halfidx = ((ks * 8 + np) * 32 + lane) * 8 + (odd * 2 + hi) * 2 + comp;
    g_W2h[((p * 2 + nhalf) * 4 + c) * 8192 + halfidx] = hv;
}

// ---------------------------------------------------------------------------
// ab_kernel: P = x @ W1[:128,:], Q = x @ W1[128:,:] for each of 3 predicates.
// ---------------------------------------------------------------------------
__global__ __launch_bounds__(256) void ab_kernel(
    const float* __restrict__ emb,
    const float* __restrict__ W1a,
    const float* __restrict__ W1b,
    const float* __restrict__ W1c)
{
    __shared__ float Xs[16][65];
    __shared__ float Ws[16][64];
    int z = blockIdx.z;
    int p = z >> 1, half = z & 1;
    const float* W = (p == 0 ? W1a : (p == 1 ? W1b : W1c)) + half * 128 * 256;
    int row0 = blockIdx.y * 64;
    int col0 = blockIdx.x * 64;
    int tid = threadIdx.x;
    int tr = tid >> 4, tc = tid & 15;
    float acc[4][4];
    #pragma unroll
    for (int r = 0; r < 4; r++)
        #pragma unroll
        for (int c = 0; c < 4; c++) acc[r][c] = 0.0f;

    for (int k0 = 0; k0 < 128; k0 += 16){
        int kx = tid & 15, rx = tid >> 4;
        #pragma unroll
        for (int pp = 0; pp < 4; pp++)
            Xs[kx][rx + pp*16] = emb[(row0 + rx + pp*16)*128 + k0 + kx];
        int cw = tid & 63, kw = tid >> 6;
        #pragma unroll
        for (int pp = 0; pp < 4; pp++)
            Ws[kw + pp*4][cw] = W[(k0 + kw + pp*4)*256 + col0 + cw];
        __syncthreads();
        #pragma unroll
        for (int k = 0; k < 16; k++){
            float a[4], bv[4];
            #pragma unroll
            for (int r = 0; r < 4; r++) a[r] = Xs[k][tr*4 + r];
            #pragma unroll
            for (int c = 0; c < 4; c++) bv[c] = Ws[k][tc*4 + c];
            #pragma unroll
            for (int r = 0; r < 4; r++)
                #pragma unroll
                for (int c = 0; c < 4; c++)
                    acc[r][c] = fmaf(a[r], bv[c], acc[r][c]);
        }
        __syncthreads();
    }
    float* out = g_AB + (size_t)z * 2048 * 256;
    #pragma unroll
    for (int r = 0; r < 4; r++){
        float4 v = make_float4(acc[r][0], acc[r][1], acc[r][2], acc[r][3]);
        *(float4*)&out[(row0 + tr*4 + r)*256 + col0 + tc*4] = v;
    }
}

// ---------------------------------------------------------------------------
// p0_kernel: arity-1 residual MLP. 32 rows per block, 64 blocks (2x the
// parallelism of the 64-row version; occ was 12% at 32 blocks).
// ---------------------------------------------------------------------------
__global__ __launch_bounds__(256) void p0_kernel(
    const float* __restrict__ emb,
    const float* __restrict__ W1,
    const float* __restrict__ b1,
    const float* __restrict__ W2,
    const float* __restrict__ b2,
    float* __restrict__ out)
{
    __shared__ float buf[128][33];   // x^T, then h^T : [k][row], 32 rows
    __shared__ float wch[16][128];
    __shared__ float bias[128];
    int row0 = blockIdx.x * 32;
    int tid = threadIdx.x;
    int tr = tid >> 5, tc = tid & 31;

    for (int idx = tid; idx < 32*128; idx += 256){
        int k = idx & 127, r = idx >> 7;
        buf[k][r] = emb[(row0 + r)*128 + k];
    }
    if (tid < 128) bias[tid] = b1[tid];
    __syncthreads();

    float acc[4][4];
    #pragma unroll
    for (int r = 0; r < 4; r++)
        #pragma unroll
        for (int c = 0; c < 4; c++) acc[r][c] = 0.0f;

    for (int k0 = 0; k0 < 128; k0 += 16){
        #pragma unroll
        for (int pp = 0; pp < 8; pp++){
            int idx = tid + pp*256;
            int c = idx & 127, kk = idx >> 7;
            wch[kk][c] = W1[(k0 + kk)*128 + c];
        }
        __syncthreads();
        #pragma unroll
        for (int k = 0; k < 16; k++){
            float a[4], bv[4];
            #pragma unroll
            for (int r = 0; r < 4; r++) a[r] = buf[k0 + k][tr*4 + r];
            #pragma unroll
            for (int c = 0; c < 4; c++) bv[c] = wch[k][tc*4 + c];
            #pragma unroll
            for (int r = 0; r < 4; r++)
                #pragma unroll
                for (int c = 0; c < 4; c++)
                    acc[r][c] = fmaf(a[r], bv[c], acc[r][c]);
        }
        __syncthreads();
    }

    float hval[4][4];
    #pragma unroll
    for (int r = 0; r < 4; r++)
        #pragma unroll
        for (int c = 0; c < 4; c++)
            hval[r][c] = mish_f(acc[r][c] + bias[tc*4 + c]);
    __syncthreads();
    #pragma unroll
    for (int r = 0; r < 4; r++)
        #pragma unroll
        for (int c = 0; c < 4; c++)
            buf[tc*4 + c][tr*4 + r] = hval[r][c];
    if (tid < 128) bias[tid] = b2[tid];

    float acc2[4][4];
    #pragma unroll
    for (int r = 0; r < 4; r++)
        #pragma unroll
        for (int c = 0; c < 4; c++) acc2[r][c] = 0.0f;

    for (int k0 = 0; k0 < 128; k0 += 16){
        #pragma unroll
        for (int pp = 0; pp < 8; pp++){
            int idx = tid + pp*256;
            int c = idx & 127, kk = idx >> 7;
            wch[kk][c] = W2[(k0 + kk)*128 + c];
        }
        __syncthreads();
        #pragma unroll
        for (int k = 0; k < 16; k++){
            float a[4], bv[4];
            #pragma unroll
            for (int r = 0; r < 4; r++) a[r] = buf[k0 + k][tr*4 + r];
            #pragma unroll
            for (int c = 0; c < 4; c++) bv[c] = wch[k][tc*4 + c];
            #pragma unroll
            for (int r = 0; r < 4; r++)
                #pragma unroll
                for (int c = 0; c < 4; c++)
                    acc2[r][c] = fmaf(a[r], bv[c], acc2[r][c]);
        }
        __syncthreads();
    }

    #pragma unroll
    for (int r = 0; r < 4; r++){
        int row = row0 + tr*4 + r;
        float4 x = *(const float4*)&emb[row*128 + tc*4];
        float4 o = make_float4(x.x + acc2[r][0] + bias[tc*4+0],
                               x.y + acc2[r][1] + bias[tc*4+1],
                               x.z + acc2[r][2] + bias[tc*4+2],
                               x.w + acc2[r][3] + bias[tc*4+3]);
        *(float4*)&out[row*128 + tc*4] = o;
    }
}

// ---------------------------------------------------------------------------
// pair_mma_kernel: arity-2 via fp16 mma.sync (m16n8k16, f32 acc).
// MERGED N: block = (pred p, ti). M=64 (j rows), N=256 (full), K=256 in 4
// chunks. 256 threads, 8 warps (2M x 4N), warp tile 32x64, acc 64 regs.
// Producer identical to R7 (mish computed ONCE per element now). W2 chunk =
// both nhalf fragment sections (32KB) via cp.async, double buffered.
// __launch_bounds__(256,2): 2 CTAs/SM, 16 warps.
// SMEM bytes: A0[0,8192) A1[8192,16384) B0[16384,49152) B1[49152,81920)
//             av[81920,82944) xi[82944,83456) b2[83456,84480)
// Epilogue: xj[64][132] floats overlaid at offset 0 after a sync.
// ---------------------------------------------------------------------------
#define PAIR_SMEM_BYTES 84480

#define MMA_F16(d, a, b0v, b1v) \
    asm volatile("mma.sync.aligned.m16n8k16.row.col.f32.f16.f16.f32 " \
        "{%0,%1,%2,%3}, {%4,%5,%6,%7}, {%8,%9}, {%0,%1,%2,%3};" \
        : "+f"(d[0]), "+f"(d[1]), "+f"(d[2]), "+f"(d[3]) \
        : "r"((a).x), "r"((a).y), "r"((a).z), "r"((a).w), \
          "r"(b0v), "r"(b1v))

__global__ __launch_bounds__(256, 2) void pair_mma_kernel(
    const float* __restrict__ emb,
    const float* __restrict__ b1a, const float* __restrict__ b1b, const float* __restrict__ b1c,
    const float* __restrict__ b2a, const float* __restrict__ b2b, const float* __restrict__ b2c,
    float* __restrict__ outbase)
{
    extern __shared__ char smc[];
    float* av   = (float*)(smc + 81920);
    float* xi_s = (float*)(smc + 82944);
    float* b2_s = (float*)(smc + 83456);
    U32 smem32;
    asm("{ .reg .u64 t; cvta.to.shared.u64 t, %1; cvt.u32.u64 %0, t; }"
        : "=r"(smem32) : "l"(smc));

    int p = blockIdx.y;
    const float* b1 = (p == 0) ? b1a : (p == 1) ? b1b : b1c;
    const float* b2 = (p == 0) ? b2a : (p == 1) ? b2b : b2c;
    float* outp = outbase + (size_t)p * 33554432;

    int ti = blockIdx.x;              // 0..2047 = b*64 + i
    int b = ti >> 6;
    const float* Pi = g_AB + ((size_t)(p*2) * 2048 + (size_t)ti) * 256;
    const float* Q  = g_AB + ((size_t)(p*2 + 1) * 2048 + (size_t)(b*64)) * 256;
    const uint4* W0 = (const uint4*)g_W2h + (size_t)(p*2    ) * 4096;
    const uint4* W1 = (const uint4*)g_W2h + (size_t)(p*2 + 1) * 4096;

    int t = threadIdx.x;
    int wid = t >> 5, lane = t & 31;
    int wm = wid & 1, wn = wid >> 1;
    int g = lane >> 2, tl = lane & 3;

    // av[k] = P[i][k] + b1[k]; stage xi and full b2
    av[t] = Pi[t] + b1[t];
    if (t < 32){
        float4 v = ((const float4*)(emb + (size_t)ti * 128))[t];
        *(float4*)&xi_s[t*4] = v;
    } else if (t < 96){
        int t2 = t - 32;
        float4 bv = ((const float4*)b2)[t2];
        *(float4*)&b2_s[t2*4] = bv;
    }
    __syncthreads();

    // W2 chunk async copy: both nhalf sections, 32KB total (8 uint4/thread)
    auto produceW = [&](int c, U32 Bs32){
        const uint4* s0 = W0 + c * 1024 + t;
        const uint4* s1 = W1 + c * 1024 + t;
        #pragma unroll
        for (int it = 0; it < 4; it++){
            cp16(Bs32 + (U32)(t + it*256) * 16u, s0 + it*256);
            cp16(Bs32 + 16384u + (U32)(t + it*256) * 16u, s1 + it*256);
        }
        asm volatile("cp.async.commit_group;" ::: "memory");
    };

    // A (h) fragments: 2 uint4 per thread per chunk, exact mma layout (R7)
    auto produceA = [&](int c, char* Ab){
        #pragma unroll
        for (int e = 0; e < 2; e++){
            int idx = t + e*256;
            int ks = idx >> 7;
            int mt = (idx >> 5) & 3;
            int ln = idx & 31;
            int gg = ln >> 2, tll = ln & 3;
            int j = mt*16 + gg;
            int kb = c*64 + ks*16 + 2*tll;
            const float* qr0 = Q + (size_t)j * 256 + kb;
            const float* qr1 = qr0 + 8 * 256;
            float2 qa0 = *(const float2*)qr0;
            float2 qa1 = *(const float2*)(qr0 + 8);
            float2 qb0 = *(const float2*)qr1;
            float2 qb1 = *(const float2*)(qr1 + 8);
            float2 av0 = *(const float2*)(av + kb);
            float2 av1 = *(const float2*)(av + kb + 8);
            U32 a0 = pack_h2(mish_f(av0.x + qa0.x), mish_f(av0.y + qa0.y));
            U32 a1 = pack_h2(mish_f(av0.x + qb0.x), mish_f(av0.y + qb0.y));
            U32 a2 = pack_h2(mish_f(av1.x + qa1.x), mish_f(av1.y + qa1.y));
            U32 a3 = pack_h2(mish_f(av1.x + qb1.x), mish_f(av1.y + qb1.y));
            *(uint4*)(Ab + (((ks*4 + mt)*32 + ln) << 4)) = make_uint4(a0,a1,a2,a3);
        }
    };

    float acc[2][8][4];
    #pragma unroll
    for (int mf = 0; mf < 2; mf++)
        #pragma unroll
        for (int nf = 0; nf < 8; nf++)
            #pragma unroll
            for (int u = 0; u < 4; u++) acc[mf][nf][u] = 0.0f;

    int nh = wn >> 1;                 // warp's nhalf
    int npb = (wn & 1) * 4;           // np base within nhalf section

    auto consume = [&](char* Ab, char* Bb){
        char* Bn = Bb + nh * 16384;
        #pragma unroll
        for (int ks = 0; ks < 4; ks++){
            uint4 aA = *(uint4*)(Ab + (((ks*4 + wm*2    )*32 + lane) << 4));
            uint4 aB = *(uint4*)(Ab + (((ks*4 + wm*2 + 1)*32 + lane) << 4));
            #pragma unroll
            for (int npp = 0; npp < 4; npp++){
                uint4 v = *(uint4*)(Bn + (((ks*8 + npb + npp)*32 + lane) << 4));
                MMA_F16(acc[0][2*npp    ], aA, v.x, v.y);
                MMA_F16(acc[1][2*npp    ], aB, v.x, v.y);
                MMA_F16(acc[0][2*npp + 1], aA, v.z, v.w);
                MMA_F16(acc[1][2*npp + 1], aB, v.z, v.w);
            }
        }
    };

    char* A0 = smc;          char* A1 = smc + 8192;
    char* B0 = smc + 16384;  char* B1 = smc + 49152;
    U32 B0a = smem32 + 16384, B1a = smem32 + 49152;

    produceW(0, B0a); produceA(0, A0);
    asm volatile("cp.async.wait_group 0;" ::: "memory");
    __syncthreads();
    produceW(1, B1a); produceA(1, A1); consume(A0, B0);
    asm volatile("cp.async.wait_group 0;" ::: "memory");
    __syncthreads();
    produceW(2, B0a); produceA(2, A0); consume(A1, B1);
    asm volatile("cp.async.wait_group 0;" ::: "memory");
    __syncthreads();
    produceW(3, B1a); produceA(3, A1); consume(A0, B0);
    asm volatile("cp.async.wait_group 0;" ::: "memory");
    __syncthreads();
    consume(A1, B1);

    // ---- epilogue: stage xj (rows of this batch) then fused writeback ----
    __syncthreads();                  // all buffers free
    float* xj_s = (float*)smc;        // [64][132], 33792 B (fits A0+A1+B0)
    {
        const float* embB = emb + (size_t)(b*64) * 128;
        #pragma unroll
        for (int it = 0; it < 8; it++){
            int idx = t + it*256;
            int jr = idx >> 5, c4 = idx & 31;
            float4 v = ((const float4*)(embB + (size_t)jr*128))[c4];
            *(float4*)&xj_s[jr*132 + c4*4] = v;
        }
    }
    __syncthreads();

    size_t rowbase = (size_t)ti * 64;

    #pragma unroll
    for (int mf = 0; mf < 2; mf++){
        int jr0 = wm*32 + mf*16 + g;
        int jr1 = jr0 + 8;
        float* o0 = outp + (rowbase + jr0) * 256;
        float* o1 = outp + (rowbase + jr1) * 256;
        #pragma unroll
        for (int npp = 0; npp < 4; npp++){
            #pragma unroll
            for (int inner = 0; inner < 2; inner++){
                int nf = 2*npp + inner;
                int col = nh*128 + (npb + npp)*16 + inner*8 + 2*tl;
                float add00, add01, add10, add11;
                if (nh == 0){
                    float x0 = xi_s[col], x1 = xi_s[col + 1];
                    add00 = x0; add01 = x1; add10 = x0; add11 = x1;
                } else {
                    int cc = col - 128;
                    add00 = xj_s[jr0*132 + cc];
                    add01 = xj_s[jr0*132 + cc + 1];
                    add10 = xj_s[jr1*132 + cc];
                    add11 = xj_s[jr1*132 + cc + 1];
                }
                float bb0 = b2_s[col], bb1 = b2_s[col + 1];
                float2 v0 = make_float2(acc[mf][nf][0] + add00 + bb0,
                                        acc[mf][nf][1] + add01 + bb1);
                float2 v1 = make_float2(acc[mf][nf][2] + add10 + bb0,
                                        acc[mf][nf][3] + add11 + bb1);
                *(float2*)&o0[col] = v0;
                *(float2*)&o1[col] = v1;
            }
        }
    }
}

// ---------------------------------------------------------------------------
extern "C" void kernel_launch(void* const* d_in, const int* in_sizes, int n_in,
                              void* d_out, int out_size)
{
    (void)in_sizes; (void)n_in; (void)out_size;
    const float* emb  = (const float*)d_in[0];
    const float* W1_0 = (const float*)d_in[2];
    const float* b1_0 = (const float*)d_in[3];
    const float* W2_0 = (const float*)d_in[4];
    const float* b2_0 = (const float*)d_in[5];
    const float* W1_1 = (const float*)d_in[6];
    const float* b1_1 = (const float*)d_in[7];
    const float* W2_1 = (const float*)d_in[8];
    const float* b2_1 = (const float*)d_in[9];
    const float* W1_2 = (const float*)d_in[10];
    const float* b1_2 = (const float*)d_in[11];
    const float* W2_2 = (const float*)d_in[12];
    const float* b2_2 = (const float*)d_in[13];
    const float* W1_3 = (const float*)d_in[14];
    const float* b1_3 = (const float*)d_in[15];
    const float* W2_3 = (const float*)d_in[16];
    const float* b2_3 = (const float*)d_in[17];
    float* out = (float*)d_out;

    static int smem_set = 0;
    if (!smem_set){
        cudaFuncSetAttribute(pair_mma_kernel,
                             cudaFuncAttributeMaxDynamicSharedMemorySize,
                             PAIR_SMEM_BYTES);
        smem_set = 1;
    }

    w2frag_kernel<<<768, 256>>>(W2_1, W2_2, W2_3);
    ab_kernel<<<dim3(4, 32, 6), 256>>>(emb, W1_1, W1_2, W1_3);
    p0_kernel<<<64, 256>>>(emb, W1_0, b1_0, W2_0, b2_0, out);
    pair_mma_kernel<<<dim3(2048, 3), 256, PAIR_SMEM_BYTES>>>(
        emb,
        b1_1, b1_2, b1_3,
        b2_1, b2_2, b2_3,
        out + 262144);
}

// round 13
// speedup vs baseline: 1.4369x; 1.0771x over previous
#include <cuda_runtime.h>

typedef unsigned int U32;
typedef unsigned short U16;

static __device__ __forceinline__ float mish_f(float x){
    // mish(x) = x * ((1+e^x)^2 - 1) / ((1+e^x)^2 + 1), division via
    // bit-hack reciprocal + 2 Newton iterations (FMA pipe, no MUFU.RCP).
    float e  = __expf(fminf(x, 30.0f));
    float u  = 1.0f + e;
    float u2 = u * u;
    float d  = u2 + 1.0f;
    float r  = __int_as_float(0x7EF311C2 - __float_as_int(d));
    r = r * (2.0f - d * r);
    r = r * (2.0f - d * r);
    return x * (u2 - 1.0f) * r;
}

// g_AB: [pred(3)][half(2)][row(2048)][col(256)]  (P = x@W1_top, Q = x@W1_bot)
__device__ float g_AB[6 * 2048 * 256];
// g_W2h: W2 in fp16, fragment order: [pred(3)][nhalf(2)][chunk(4)][8192 halves]
__device__ U16 g_W2h[3 * 65536];

static __device__ __forceinline__ U32 pack_h2(float lo, float hi){
    U32 r;
    asm("cvt.rn.f16x2.f32 %0, %1, %2;" : "=r"(r) : "f"(hi), "f"(lo));
    return r;
}

static __device__ __forceinline__ void cp16(U32 dst, const void* src){
    asm volatile("cp.async.cg.shared.global [%0], [%1], 16;"
                 :: "r"(dst), "l"(src) : "memory");
}

// ---------------------------------------------------------------------------
// prep bodies (fused into one kernel; all independent of each other)
// ---------------------------------------------------------------------------
static __device__ void w2frag_body(int blk,
    const float* __restrict__ W2a, const float* __restrict__ W2b,
    const float* __restrict__ W2c)
{
    int idx = blk * 256 + threadIdx.x;          // 0 .. 196607
    int p = idx >> 16;
    int rem = idx & 65535;
    int k = rem >> 8, n = rem & 255;
    const float* W2 = (p == 0) ? W2a : (p == 1) ? W2b : W2c;
    float v = W2[k * 256 + n];
    U16 hv;
    asm("{ .reg .f16 t; cvt.rn.f16.f32 t, %1; mov.b16 %0, t; }" : "=h"(hv) : "f"(v));
    int c = k >> 6, kk = k & 63;
    int ks = kk >> 4, r = kk & 15;
    int hi = r >> 3, r8 = r & 7, tl = r8 >> 1, comp = r8 & 1;
    int nhalf = n >> 7, nl = n & 127;
    int nt = nl >> 3, np = nt >> 1, odd = nt & 1, g = nl & 7;
    int lane = g * 4 + tl;
    int halfidx = ((ks * 8 + np) * 32 + lane) * 8 + (odd * 2 + hi) * 2 + comp;
    g_W2h[((p * 2 + nhalf) * 4 + c) * 8192 + halfidx] = hv;
}

static __device__ void ab_body(float* sh,
    const float* __restrict__ emb,
    const float* __restrict__ W1a, const float* __restrict__ W1b,
    const float* __restrict__ W1c,
    int bx, int by, int z)
{
    float (*Xs)[65] = (float(*)[65])sh;
    float (*Ws)[64] = (float(*)[64])(sh + 16*65);
    int p = z >> 1, half = z & 1;
    const float* W = (p == 0 ? W1a : (p == 1 ? W1b : W1c)) + half * 128 * 256;
    int row0 = by * 64;
    int col0 = bx * 64;
    int tid = threadIdx.x;
    int tr = tid >> 4, tc = tid & 15;
    float acc[4][4];
    #pragma unroll
    for (int r = 0; r < 4; r++)
        #pragma unroll
        for (int c = 0; c < 4; c++) acc[r][c] = 0.0f;

    for (int k0 = 0; k0 < 128; k0 += 16){
        int kx = tid & 15, rx = tid >> 4;
        #pragma unroll
        for (int pp = 0; pp < 4; pp++)
            Xs[kx][rx + pp*16] = emb[(row0 + rx + pp*16)*128 + k0 + kx];
        int cw = tid & 63, kw = tid >> 6;
        #pragma unroll
        for (int pp = 0; pp < 4; pp++)
            Ws[kw + pp*4][cw] = W[(k0 + kw + pp*4)*256 + col0 + cw];
        __syncthreads();
        #pragma unroll
        for (int k = 0; k < 16; k++){
            float a[4], bv[4];
            #pragma unroll
            for (int r = 0; r < 4; r++) a[r] = Xs[k][tr*4 + r];
            #pragma unroll
            for (int c = 0; c < 4; c++) bv[c] = Ws[k][tc*4 + c];
            #pragma unroll
            for (int r = 0; r < 4; r++)
                #pragma unroll
                for (int c = 0; c < 4; c++)
                    acc[r][c] = fmaf(a[r], bv[c], acc[r][c]);
        }
        __syncthreads();
    }
    float* out = g_AB + (size_t)z * 2048 * 256;
    #pragma unroll
    for (int r = 0; r < 4; r++){
        float4 v = make_float4(acc[r][0], acc[r][1], acc[r][2], acc[r][3]);
        *(float4*)&out[(row0 + tr*4 + r)*256 + col0 + tc*4] = v;
    }
}

static __device__ void p0_body(float* sh,
    const float* __restrict__ emb,
    const float* __restrict__ W1, const float* __restrict__ b1,
    const float* __restrict__ W2, const float* __restrict__ b2,
    float* __restrict__ out, int blk)
{
    float (*buf)[33] = (float(*)[33])sh;                 // 128 x 33
    float (*wch)[128] = (float(*)[128])(sh + 4224);      // 16 x 128
    float* bias = sh + 4224 + 2048;
    int row0 = blk * 32;
    int tid = threadIdx.x;
    int tr = tid >> 5, tc = tid & 31;

    for (int idx = tid; idx < 32*128; idx += 256){
        int k = idx & 127, r = idx >> 7;
        buf[k][r] = emb[(row0 + r)*128 + k];
    }
    if (tid < 128) bias[tid] = b1[tid];
    __syncthreads();

    float acc[4][4];
    #pragma unroll
    for (int r = 0; r < 4; r++)
        #pragma unroll
        for (int c = 0; c < 4; c++) acc[r][c] = 0.0f;

    for (int k0 = 0; k0 < 128; k0 += 16){
        #pragma unroll
        for (int pp = 0; pp < 8; pp++){
            int idx = tid + pp*256;
            int c = idx & 127, kk = idx >> 7;
            wch[kk][c] = W1[(k0 + kk)*128 + c];
        }
        __syncthreads();
        #pragma unroll
        for (int k = 0; k < 16; k++){
            float a[4], bv[4];
            #pragma unroll
            for (int r = 0; r < 4; r++) a[r] = buf[k0 + k][tr*4 + r];
            #pragma unroll
            for (int c = 0; c < 4; c++) bv[c] = wch[k][tc*4 + c];
            #pragma unroll
            for (int r = 0; r < 4; r++)
                #pragma unroll
                for (int c = 0; c < 4; c++)
                    acc[r][c] = fmaf(a[r], bv[c], acc[r][c]);
        }
        __syncthreads();
    }

    float hval[4][4];
    #pragma unroll
    for (int r = 0; r < 4; r++)
        #pragma unroll
        for (int c = 0; c < 4; c++)
            hval[r][c] = mish_f(acc[r][c] + bias[tc*4 + c]);
    __syncthreads();
    #pragma unroll
    for (int r = 0; r < 4; r++)
        #pragma unroll
        for (int c = 0; c < 4; c++)
            buf[tc*4 + c][tr*4 + r] = hval[r][c];
    if (tid < 128) bias[tid] = b2[tid];

    float acc2[4][4];
    #pragma unroll
    for (int r = 0; r < 4; r++)
        #pragma unroll
        for (int c = 0; c < 4; c++) acc2[r][c] = 0.0f;

    for (int k0 = 0; k0 < 128; k0 += 16){
        #pragma unroll
        for (int pp = 0; pp < 8; pp++){
            int idx = tid + pp*256;
            int c = idx & 127, kk = idx >> 7;
            wch[kk][c] = W2[(k0 + kk)*128 + c];
        }
        __syncthreads();
        #pragma unroll
        for (int k = 0; k < 16; k++){
            float a[4], bv[4];
            #pragma unroll
            for (int r = 0; r < 4; r++) a[r] = buf[k0 + k][tr*4 + r];
            #pragma unroll
            for (int c = 0; c < 4; c++) bv[c] = wch[k][tc*4 + c];
            #pragma unroll
            for (int r = 0; r < 4; r++)
                #pragma unroll
                for (int c = 0; c < 4; c++)
                    acc2[r][c] = fmaf(a[r], bv[c], acc2[r][c]);
        }
        __syncthreads();
    }

    #pragma unroll
    for (int r = 0; r < 4; r++){
        int row = row0 + tr*4 + r;
        float4 x = *(const float4*)&emb[row*128 + tc*4];
        float4 o = make_float4(x.x + acc2[r][0] + bias[tc*4+0],
                               x.y + acc2[r][1] + bias[tc*4+1],
                               x.z + acc2[r][2] + bias[tc*4+2],
                               x.w + acc2[r][3] + bias[tc*4+3]);
        *(float4*)&out[row*128 + tc*4] = o;
    }
}

// prep_kernel: blocks [0,768) = ab, [768,1536) = w2frag, [1536,1600) = p0.
#define PREP_SMEM_BYTES 25600
__global__ __launch_bounds__(256) void prep_kernel(
    const float* __restrict__ emb,
    const float* __restrict__ W1_1, const float* __restrict__ W1_2,
    const float* __restrict__ W1_3,
    const float* __restrict__ W2_1, const float* __restrict__ W2_2,
    const float* __restrict__ W2_3,
    const float* __restrict__ W1_0, const float* __restrict__ b1_0,
    const float* __restrict__ W2_0, const float* __restrict__ b2_0,
    float* __restrict__ out)
{
    extern __shared__ float sh[];
    int bz = blockIdx.x;
    if (bz < 768){
        ab_body(sh, emb, W1_1, W1_2, W1_3, bz & 3, (bz >> 2) & 31, bz >> 7);
    } else if (bz < 1536){
        w2frag_body(bz - 768, W2_1, W2_2, W2_3);
    } else {
        p0_body(sh, emb, W1_0, b1_0, W2_0, b2_0, out, bz - 1536);
    }
}

// ---------------------------------------------------------------------------
// pair_mma_kernel: arity-2 via fp16 mma.sync (m16n8k16, f32 acc).
// Block = (pred p, ti). M=64 (j rows), N=256, K=256. Phase-form pipeline:
// all 4 A chunks produced up front (A0..A3, 32KB), W2 chunks {0,1} then
// {2,3} cp.async'd into B0/B1 (32KB each, both nhalf sections). Consumes run
// in back-to-back pairs (128 MMAs/warp between barriers; 3 main syncs).
// 256 threads, 8 warps (2M x 4N), warp tile 32x64, acc 64 regs.
// __launch_bounds__(256,2): 2 CTAs/SM.
// SMEM bytes: A0..A3 [0,32768) B0[32768,65536) B1[65536,98304)
//             av[98304,99328) xi[99328,99840) b2[99840,100864)
// Epilogue: xj[64][132] floats overlaid at offset 0 after a sync.
// ---------------------------------------------------------------------------
#define PAIR_SMEM_BYTES 100864

#define MMA_F16(d, a, b0v, b1v) \
    asm volatile("mma.sync.aligned.m16n8k16.row.col.f32.f16.f16.f32 " \
        "{%0,%1,%2,%3}, {%4,%5,%6,%7}, {%8,%9}, {%0,%1,%2,%3};" \
        : "+f"(d[0]), "+f"(d[1]), "+f"(d[2]), "+f"(d[3]) \
        : "r"((a).x), "r"((a).y), "r"((a).z), "r"((a).w), \
          "r"(b0v), "r"(b1v))

__global__ __launch_bounds__(256, 2) void pair_mma_kernel(
    const float* __restrict__ emb,
    const float* __restrict__ b1a, const float* __restrict__ b1b, const float* __restrict__ b1c,
    const float* __restrict__ b2a, const float* __restrict__ b2b, const float* __restrict__ b2c,
    float* __restrict__ outbase)
{
    extern __shared__ char smc[];
    float* av   = (float*)(smc + 98304);
    float* xi_s = (float*)(smc + 99328);
    float* b2_s = (float*)(smc + 99840);
    U32 smem32;
    asm("{ .reg .u64 t; cvta.to.shared.u64 t, %1; cvt.u32.u64 %0, t; }"
        : "=r"(smem32) : "l"(smc));

    int p = blockIdx.y;
    const float* b1 = (p == 0) ? b1a : (p == 1) ? b1b : b1c;
    const float* b2 = (p == 0) ? b2a : (p == 1) ? b2b : b2c;
    float* outp = outbase + (size_t)p * 33554432;

    int ti = blockIdx.x;              // 0..2047 = b*64 + i
    int b = ti >> 6;
    const float* Pi = g_AB + ((size_t)(p*2) * 2048 + (size_t)ti) * 256;
    const float* Q  = g_AB + ((size_t)(p*2 + 1) * 2048 + (size_t)(b*64)) * 256;
    const uint4* W0 = (const uint4*)g_W2h + (size_t)(p*2    ) * 4096;
    const uint4* W1 = (const uint4*)g_W2h + (size_t)(p*2 + 1) * 4096;

    int t = threadIdx.x;
    int wid = t >> 5, lane = t & 31;
    int wm = wid & 1, wn = wid >> 1;
    int g = lane >> 2, tl = lane & 3;

    // av[k] = P[i][k] + b1[k]; stage xi and full b2
    av[t] = Pi[t] + b1[t];
    if (t < 32){
        float4 v = ((const float4*)(emb + (size_t)ti * 128))[t];
        *(float4*)&xi_s[t*4] = v;
    } else if (t < 96){
        int t2 = t - 32;
        float4 bv = ((const float4*)b2)[t2];
        *(float4*)&b2_s[t2*4] = bv;
    }

    // W2 chunk async copy: both nhalf sections, 32KB total (8 uint4/thread)
    auto produceW = [&](int c, U32 Bs32){
        const uint4* s0 = W0 + c * 1024 + t;
        const uint4* s1 = W1 + c * 1024 + t;
        #pragma unroll
        for (int it = 0; it < 4; it++){
            cp16(Bs32 + (U32)(t + it*256) * 16u, s0 + it*256);
            cp16(Bs32 + 16384u + (U32)(t + it*256) * 16u, s1 + it*256);
        }
        asm volatile("cp.async.commit_group;" ::: "memory");
    };

    // A (h) fragments: 2 uint4 per thread per chunk, exact mma layout
    auto produceA = [&](int c, char* Ab){
        #pragma unroll
        for (int e = 0; e < 2; e++){
            int idx = t + e*256;
            int ks = idx >> 7;
            int mt = (idx >> 5) & 3;
            int ln = idx & 31;
            int gg = ln >> 2, tll = ln & 3;
            int j = mt*16 + gg;
            int kb = c*64 + ks*16 + 2*tll;
            const float* qr0 = Q + (size_t)j * 256 + kb;
            const float* qr1 = qr0 + 8 * 256;
            float2 qa0 = *(const float2*)qr0;
            float2 qa1 = *(const float2*)(qr0 + 8);
            float2 qb0 = *(const float2*)qr1;
            float2 qb1 = *(const float2*)(qr1 + 8);
            float2 av0 = *(const float2*)(av + kb);
            float2 av1 = *(const float2*)(av + kb + 8);
            U32 a0 = pack_h2(mish_f(av0.x + qa0.x), mish_f(av0.y + qa0.y));
            U32 a1 = pack_h2(mish_f(av0.x + qb0.x), mish_f(av0.y + qb0.y));
            U32 a2 = pack_h2(mish_f(av1.x + qa1.x), mish_f(av1.y + qa1.y));
            U32 a3 = pack_h2(mish_f(av1.x + qb1.x), mish_f(av1.y + qb1.y));
            *(uint4*)(Ab + (((ks*4 + mt)*32 + ln) << 4)) = make_uint4(a0,a1,a2,a3);
        }
    };

    float acc[2][8][4];
    #pragma unroll
    for (int mf = 0; mf < 2; mf++)
        #pragma unroll
        for (int nf = 0; nf < 8; nf++)
            #pragma unroll
            for (int u = 0; u < 4; u++) acc[mf][nf][u] = 0.0f;

    int nh = wn >> 1;                 // warp's nhalf
    int npb = (wn & 1) * 4;           // np base within nhalf section

    auto consume = [&](char* Ab, char* Bb){
        char* Bn = Bb + nh * 16384;
        #pragma unroll
        for (int ks = 0; ks < 4; ks++){
            uint4 aA = *(uint4*)(Ab + (((ks*4 + wm*2    )*32 + lane) << 4));
            uint4 aB = *(uint4*)(Ab + (((ks*4 + wm*2 + 1)*32 + lane) << 4));
            #pragma unroll
            for (int npp = 0; npp < 4; npp++){
                uint4 v = *(uint4*)(Bn + (((ks*8 + npb + npp)*32 + lane) << 4));
                MMA_F16(acc[0][2*npp    ], aA, v.x, v.y);
                MMA_F16(acc[1][2*npp    ], aB, v.x, v.y);
                MMA_F16(acc[0][2*npp + 1], aA, v.z, v.w);
                MMA_F16(acc[1][2*npp + 1], aB, v.z, v.w);
            }
        }
    };

    char* A0 = smc;          char* A1 = smc + 8192;
    char* A2 = smc + 16384;  char* A3 = smc + 24576;
    char* B0 = smc + 32768;  char* B1 = smc + 65536;
    U32 B0a = smem32 + 32768, B1a = smem32 + 65536;

    // phase 1: kick W{0,1}; av must be visible before produceA
    produceW(0, B0a);
    produceW(1, B1a);
    __syncthreads();                  // av/xi/b2 visible
    produceA(0, A0); produceA(1, A1); produceA(2, A2); produceA(3, A3);
    asm volatile("cp.async.wait_group 0;" ::: "memory");
    __syncthreads();                  // A + B{0,1} visible

    consume(A0, B0);
    consume(A1, B1);
    __syncthreads();                  // B free

    produceW(2, B0a);
    produceW(3, B1a);
    asm volatile("cp.async.wait_group 0;" ::: "memory");
    __syncthreads();                  // B{2,3} visible

    consume(A2, B0);
    consume(A3, B1);

    // ---- epilogue: stage xj then fused writeback ----
    __syncthreads();                  // A buffers free
    float* xj_s = (float*)smc;        // [64][132], 33792 B (A region + B0 head)
    {
        const float* embB = emb + (size_t)(b*64) * 128;
        #pragma unroll
        for (int it = 0; it < 8; it++){
            int idx = t + it*256;
            int jr = idx >> 5, c4 = idx & 31;
            float4 v = ((const float4*)(embB + (size_t)jr*128))[c4];
            *(float4*)&xj_s[jr*132 + c4*4] = v;
        }
    }
    __syncthreads();

    size_t rowbase = (size_t)ti * 64;

    #pragma unroll
    for (int mf = 0; mf < 2; mf++){
        int jr0 = wm*32 + mf*16 + g;
        int jr1 = jr0 + 8;
        float* o0 = outp + (rowbase + jr0) * 256;
        float* o1 = outp + (rowbase + jr1) * 256;
        #pragma unroll
        for (int npp = 0; npp < 4; npp++){
            #pragma unroll
            for (int inner = 0; inner < 2; inner++){
                int nf = 2*npp + inner;
                int col = nh*128 + (npb + npp)*16 + inner*8 + 2*tl;
                float add00, add01, add10, add11;
                if (nh == 0){
                    float x0 = xi_s[col], x1 = xi_s[col + 1];
                    add00 = x0; add01 = x1; add10 = x0; add11 = x1;
                } else {
                    int cc = col - 128;
                    add00 = xj_s[jr0*132 + cc];
                    add01 = xj_s[jr0*132 + cc + 1];
                    add10 = xj_s[jr1*132 + cc];
                    add11 = xj_s[jr1*132 + cc + 1];
                }
                float bb0 = b2_s[col], bb1 = b2_s[col + 1];
                float2 v0 = make_float2(acc[mf][nf][0] + add00 + bb0,
                                        acc[mf][nf][1] + add01 + bb1);
                float2 v1 = make_float2(acc[mf][nf][2] + add10 + bb0,
                                        acc[mf][nf][3] + add11 + bb1);
                *(float2*)&o0[col] = v0;
                *(float2*)&o1[col] = v1;
            }
        }
    }
}

// ---------------------------------------------------------------------------
extern "C" void kernel_launch(void* const* d_in, const int* in_sizes, int n_in,
                              void* d_out, int out_size)
{
    (void)in_sizes; (void)n_in; (void)out_size;
    const float* emb  = (const float*)d_in[0];
    const float* W1_0 = (const float*)d_in[2];
    const float* b1_0 = (const float*)d_in[3];
    const float* W2_0 = (const float*)d_in[4];
    const float* b2_0 = (const float*)d_in[5];
    const float* W1_1 = (const float*)d_in[6];
    const float* b1_1 = (const float*)d_in[7];
    const float* W2_1 = (const float*)d_in[8];
    const float* b2_1 = (const float*)d_in[9];
    const float* W1_2 = (const float*)d_in[10];
    const float* b1_2 = (const float*)d_in[11];
    const float* W2_2 = (const float*)d_in[12];
    const float* b2_2 = (const float*)d_in[13];
    const float* W1_3 = (const float*)d_in[14];
    const float* b1_3 = (const float*)d_in[15];
    const float* W2_3 = (const float*)d_in[16];
    const float* b2_3 = (const float*)d_in[17];
    float* out = (float*)d_out;

    static int smem_set = 0;
    if (!smem_set){
        cudaFuncSetAttribute(pair_mma_kernel,
                             cudaFuncAttributeMaxDynamicSharedMemorySize,
                             PAIR_SMEM_BYTES);
        smem_set = 1;
    }

    prep_kernel<<<1600, 256, PREP_SMEM_BYTES>>>(
        emb,
        W1_1, W1_2, W1_3,
        W2_1, W2_2, W2_3,
        W1_0, b1_0, W2_0, b2_0,
        out);
    pair_mma_kernel<<<dim3(2048, 3), 256, PAIR_SMEM_BYTES>>>(
        emb,
        b1_1, b1_2, b1_3,
        b2_1, b2_2, b2_3,
        out + 262144);
}

// round 14
// speedup vs baseline: 1.4988x; 1.0431x over previous
#include <cuda_runtime.h>

typedef unsigned int U32;
typedef unsigned short U16;

static __device__ __forceinline__ float mish_f(float x){
    // mish(x) = x * ((1+e^x)^2 - 1) / ((1+e^x)^2 + 1), division via
    // bit-hack reciprocal + 2 Newton iterations (FMA pipe, no MUFU.RCP).
    float e  = __expf(fminf(x, 30.0f));
    float u  = 1.0f + e;
    float u2 = u * u;
    float d  = u2 + 1.0f;
    float r  = __int_as_float(0x7EF311C2 - __float_as_int(d));
    r = r * (2.0f - d * r);
    r = r * (2.0f - d * r);
    return x * (u2 - 1.0f) * r;
}

// g_AB: [pred(3)][half(2)][row(2048)][col(256)]  (P = x@W1_top, Q = x@W1_bot)
__device__ float g_AB[6 * 2048 * 256];
// g_W2h: W2 in fp16, fragment order: [pred(3)][nhalf(2)][chunk(4)][8192 halves]
__device__ U16 g_W2h[3 * 65536];

static __device__ __forceinline__ U32 pack_h2(float lo, float hi){
    U32 r;
    asm("cvt.rn.f16x2.f32 %0, %1, %2;" : "=r"(r) : "f"(hi), "f"(lo));
    return r;
}

static __device__ __forceinline__ void cp16(U32 dst, const void* src){
    asm volatile("cp.async.cg.shared.global [%0], [%1], 16;"
                 :: "r"(dst), "l"(src) : "memory");
}

// ---------------------------------------------------------------------------
// prep bodies (fused into one kernel; all independent of each other)
// ---------------------------------------------------------------------------
static __device__ void w2frag_body(int blk,
    const float* __restrict__ W2a, const float* __restrict__ W2b,
    const float* __restrict__ W2c)
{
    int idx = blk * 256 + threadIdx.x;          // 0 .. 196607
    int p = idx >> 16;
    int rem = idx & 65535;
    int k = rem >> 8, n = rem & 255;
    const float* W2 = (p == 0) ? W2a : (p == 1) ? W2b : W2c;
    float v = W2[k * 256 + n];
    U16 hv;
    asm("{ .reg .f16 t; cvt.rn.f16.f32 t, %1; mov.b16 %0, t; }" : "=h"(hv) : "f"(v));
    int c = k >> 6, kk = k & 63;
    int ks = kk >> 4, r = kk & 15;
    int hi = r >> 3, r8 = r & 7, tl = r8 >> 1, comp = r8 & 1;
    int nhalf = n >> 7, nl = n & 127;
    int nt = nl >> 3, np = nt >> 1, odd = nt & 1, g = nl & 7;
    int lane = g * 4 + tl;
    int halfidx = ((ks * 8 + np) * 32 + lane) * 8 + (odd * 2 + hi) * 2 + comp;
    g_W2h[((p * 2 + nhalf) * 4 + c) * 8192 + halfidx] = hv;
}

// ab: full-tile single-sync version. Xs[128 k][65 pad] + Ws[128 k][64].
static __device__ void ab_body(float* sh,
    const float* __restrict__ emb,
    const float* __restrict__ W1a, const float* __restrict__ W1b,
    const float* __restrict__ W1c,
    int bx, int by, int z)
{
    float (*Xs)[65] = (float(*)[65])sh;
    float (*Ws)[64] = (float(*)[64])(sh + 128*65);
    int p = z >> 1, half = z & 1;
    const float* W = (p == 0 ? W1a : (p == 1 ? W1b : W1c)) + half * 128 * 256;
    int row0 = by * 64;
    int col0 = bx * 64;
    int tid = threadIdx.x;
    int tr = tid >> 4, tc = tid & 15;

    #pragma unroll
    for (int it = 0; it < 32; it++){
        int idx = tid + it*256;       // idx = r*128 + k
        int r = idx >> 7, k = idx & 127;
        Xs[k][r] = emb[(row0 + r)*128 + k];
    }
    #pragma unroll
    for (int it = 0; it < 32; it++){
        int idx = tid + it*256;       // idx = k*64 + c
        int k = idx >> 6, c = idx & 63;
        Ws[k][c] = W[k*256 + col0 + c];
    }
    __syncthreads();

    float acc[4][4];
    #pragma unroll
    for (int r = 0; r < 4; r++)
        #pragma unroll
        for (int c = 0; c < 4; c++) acc[r][c] = 0.0f;

    #pragma unroll 4
    for (int k = 0; k < 128; k++){
        float a[4], bv[4];
        #pragma unroll
        for (int r = 0; r < 4; r++) a[r] = Xs[k][tr*4 + r];
        #pragma unroll
        for (int c = 0; c < 4; c++) bv[c] = Ws[k][tc*4 + c];
        #pragma unroll
        for (int r = 0; r < 4; r++)
            #pragma unroll
            for (int c = 0; c < 4; c++)
                acc[r][c] = fmaf(a[r], bv[c], acc[r][c]);
    }

    float* out = g_AB + (size_t)z * 2048 * 256;
    #pragma unroll
    for (int r = 0; r < 4; r++){
        float4 v = make_float4(acc[r][0], acc[r][1], acc[r][2], acc[r][3]);
        *(float4*)&out[(row0 + tr*4 + r)*256 + col0 + tc*4] = v;
    }
}

static __device__ void p0_body(float* sh,
    const float* __restrict__ emb,
    const float* __restrict__ W1, const float* __restrict__ b1,
    const float* __restrict__ W2, const float* __restrict__ b2,
    float* __restrict__ out, int blk)
{
    float (*buf)[33] = (float(*)[33])sh;                 // 128 x 33
    float (*wch)[128] = (float(*)[128])(sh + 4224);      // 16 x 128
    float* bias = sh + 4224 + 2048;
    int row0 = blk * 32;
    int tid = threadIdx.x;
    int tr = tid >> 5, tc = tid & 31;

    for (int idx = tid; idx < 32*128; idx += 256){
        int k = idx & 127, r = idx >> 7;
        buf[k][r] = emb[(row0 + r)*128 + k];
    }
    if (tid < 128) bias[tid] = b1[tid];
    __syncthreads();

    float acc[4][4];
    #pragma unroll
    for (int r = 0; r < 4; r++)
        #pragma unroll
        for (int c = 0; c < 4; c++) acc[r][c] = 0.0f;

    for (int k0 = 0; k0 < 128; k0 += 16){
        #pragma unroll
        for (int pp = 0; pp < 8; pp++){
            int idx = tid + pp*256;
            int c = idx & 127, kk = idx >> 7;
            wch[kk][c] = W1[(k0 + kk)*128 + c];
        }
        __syncthreads();
        #pragma unroll
        for (int k = 0; k < 16; k++){
            float a[4], bv[4];
            #pragma unroll
            for (int r = 0; r < 4; r++) a[r] = buf[k0 + k][tr*4 + r];
            #pragma unroll
            for (int c = 0; c < 4; c++) bv[c] = wch[k][tc*4 + c];
            #pragma unroll
            for (int r = 0; r < 4; r++)
                #pragma unroll
                for (int c = 0; c < 4; c++)
                    acc[r][c] = fmaf(a[r], bv[c], acc[r][c]);
        }
        __syncthreads();
    }

    float hval[4][4];
    #pragma unroll
    for (int r = 0; r < 4; r++)
        #pragma unroll
        for (int c = 0; c < 4; c++)
            hval[r][c] = mish_f(acc[r][c] + bias[tc*4 + c]);
    __syncthreads();
    #pragma unroll
    for (int r = 0; r < 4; r++)
        #pragma unroll
        for (int c = 0; c < 4; c++)
            buf[tc*4 + c][tr*4 + r] = hval[r][c];
    if (tid < 128) bias[tid] = b2[tid];

    float acc2[4][4];
    #pragma unroll
    for (int r = 0; r < 4; r++)
        #pragma unroll
        for (int c = 0; c < 4; c++) acc2[r][c] = 0.0f;

    for (int k0 = 0; k0 < 128; k0 += 16){
        #pragma unroll
        for (int pp = 0; pp < 8; pp++){
            int idx = tid + pp*256;
            int c = idx & 127, kk = idx >> 7;
            wch[kk][c] = W2[(k0 + kk)*128 + c];
        }
        __syncthreads();
        #pragma unroll
        for (int k = 0; k < 16; k++){
            float a[4], bv[4];
            #pragma unroll
            for (int r = 0; r < 4; r++) a[r] = buf[k0 + k][tr*4 + r];
            #pragma unroll
            for (int c = 0; c < 4; c++) bv[c] = wch[k][tc*4 + c];
            #pragma unroll
            for (int r = 0; r < 4; r++)
                #pragma unroll
                for (int c = 0; c < 4; c++)
                    acc2[r][c] = fmaf(a[r], bv[c], acc2[r][c]);
        }
        __syncthreads();
    }

    #pragma unroll
    for (int r = 0; r < 4; r++){
        int row = row0 + tr*4 + r;
        float4 x = *(const float4*)&emb[row*128 + tc*4];
        float4 o = make_float4(x.x + acc2[r][0] + bias[tc*4+0],
                               x.y + acc2[r][1] + bias[tc*4+1],
                               x.z + acc2[r][2] + bias[tc*4+2],
                               x.w + acc2[r][3] + bias[tc*4+3]);
        *(float4*)&out[row*128 + tc*4] = o;
    }
}

// prep_kernel: blocks [0,768) = ab, [768,1536) = w2frag, [1536,1600) = p0.
#define PREP_SMEM_BYTES 66560
__global__ __launch_bounds__(256) void prep_kernel(
    const float* __restrict__ emb,
    const float* __restrict__ W1_1, const float* __restrict__ W1_2,
    const float* __restrict__ W1_3,
    const float* __restrict__ W2_1, const float* __restrict__ W2_2,
    const float* __restrict__ W2_3,
    const float* __restrict__ W1_0, const float* __restrict__ b1_0,
    const float* __restrict__ W2_0, const float* __restrict__ b2_0,
    float* __restrict__ out)
{
    extern __shared__ float sh[];
    int bz = blockIdx.x;
    if (bz < 768){
        ab_body(sh, emb, W1_1, W1_2, W1_3, bz & 3, (bz >> 2) & 31, bz >> 7);
    } else if (bz < 1536){
        w2frag_body(bz - 768, W2_1, W2_2, W2_3);
    } else {
        p0_body(sh, emb, W1_0, b1_0, W2_0, b2_0, out, bz - 1536);
    }
}

// ---------------------------------------------------------------------------
// pair_mma_kernel: arity-2 via fp16 mma.sync (m16n8k16, f32 acc).
// Block = (pred p, ti). M=64 (j rows), N=256, K=256. Phase-form pipeline with
// OVERLAPPED B refills: consume(A0,B0); sync; async refill B0 while
// consume(A1,B1); etc. Epilogue reads x_j residual with direct __ldg (L2-hot
// 32KB emb slab) — no smem staging, no post-consume barriers.
// 256 threads, 8 warps (2M x 4N), warp tile 32x64, acc 64 regs.
// __launch_bounds__(256,2): 2 CTAs/SM.
// SMEM bytes: A0..A3 [0,32768) B0[32768,65536) B1[65536,98304)
//             av[98304,99328) xi[99328,99840) b2[99840,100864)
// ---------------------------------------------------------------------------
#define PAIR_SMEM_BYTES 100864

#define MMA_F16(d, a, b0v, b1v) \
    asm volatile("mma.sync.aligned.m16n8k16.row.col.f32.f16.f16.f32 " \
        "{%0,%1,%2,%3}, {%4,%5,%6,%7}, {%8,%9}, {%0,%1,%2,%3};" \
        : "+f"(d[0]), "+f"(d[1]), "+f"(d[2]), "+f"(d[3]) \
        : "r"((a).x), "r"((a).y), "r"((a).z), "r"((a).w), \
          "r"(b0v), "r"(b1v))

__global__ __launch_bounds__(256, 2) void pair_mma_kernel(
    const float* __restrict__ emb,
    const float* __restrict__ b1a, const float* __restrict__ b1b, const float* __restrict__ b1c,
    const float* __restrict__ b2a, const float* __restrict__ b2b, const float* __restrict__ b2c,
    float* __restrict__ outbase)
{
    extern __shared__ char smc[];
    float* av   = (float*)(smc + 98304);
    float* xi_s = (float*)(smc + 99328);
    float* b2_s = (float*)(smc + 99840);
    U32 smem32;
    asm("{ .reg .u64 t; cvta.to.shared.u64 t, %1; cvt.u32.u64 %0, t; }"
        : "=r"(smem32) : "l"(smc));

    int p = blockIdx.y;
    const float* b1 = (p == 0) ? b1a : (p == 1) ? b1b : b1c;
    const float* b2 = (p == 0) ? b2a : (p == 1) ? b2b : b2c;
    float* outp = outbase + (size_t)p * 33554432;

    int ti = blockIdx.x;              // 0..2047 = b*64 + i
    int b = ti >> 6;
    const float* Pi = g_AB + ((size_t)(p*2) * 2048 + (size_t)ti) * 256;
    const float* Q  = g_AB + ((size_t)(p*2 + 1) * 2048 + (size_t)(b*64)) * 256;
    const uint4* W0 = (const uint4*)g_W2h + (size_t)(p*2    ) * 4096;
    const uint4* W1 = (const uint4*)g_W2h + (size_t)(p*2 + 1) * 4096;

    int t = threadIdx.x;
    int wid = t >> 5, lane = t & 31;
    int wm = wid & 1, wn = wid >> 1;
    int g = lane >> 2, tl = lane & 3;

    // av[k] = P[i][k] + b1[k]; stage xi and full b2
    av[t] = Pi[t] + b1[t];
    if (t < 32){
        float4 v = ((const float4*)(emb + (size_t)ti * 128))[t];
        *(float4*)&xi_s[t*4] = v;
    } else if (t < 96){
        int t2 = t - 32;
        float4 bv = ((const float4*)b2)[t2];
        *(float4*)&b2_s[t2*4] = bv;
    }

    // W2 chunk async copy: both nhalf sections, 32KB total (8 uint4/thread)
    auto produceW = [&](int c, U32 Bs32){
        const uint4* s0 = W0 + c * 1024 + t;
        const uint4* s1 = W1 + c * 1024 + t;
        #pragma unroll
        for (int it = 0; it < 4; it++){
            cp16(Bs32 + (U32)(t + it*256) * 16u, s0 + it*256);
            cp16(Bs32 + 16384u + (U32)(t + it*256) * 16u, s1 + it*256);
        }
        asm volatile("cp.async.commit_group;" ::: "memory");
    };

    // A (h) fragments: 2 uint4 per thread per chunk, exact mma layout
    auto produceA = [&](int c, char* Ab){
        #pragma unroll
        for (int e = 0; e < 2; e++){
            int idx = t + e*256;
            int ks = idx >> 7;
            int mt = (idx >> 5) & 3;
            int ln = idx & 31;
            int gg = ln >> 2, tll = ln & 3;
            int j = mt*16 + gg;
            int kb = c*64 + ks*16 + 2*tll;
            const float* qr0 = Q + (size_t)j * 256 + kb;
            const float* qr1 = qr0 + 8 * 256;
            float2 qa0 = *(const float2*)qr0;
            float2 qa1 = *(const float2*)(qr0 + 8);
            float2 qb0 = *(const float2*)qr1;
            float2 qb1 = *(const float2*)(qr1 + 8);
            float2 av0 = *(const float2*)(av + kb);
            float2 av1 = *(const float2*)(av + kb + 8);
            U32 a0 = pack_h2(mish_f(av0.x + qa0.x), mish_f(av0.y + qa0.y));
            U32 a1 = pack_h2(mish_f(av0.x + qb0.x), mish_f(av0.y + qb0.y));
            U32 a2 = pack_h2(mish_f(av1.x + qa1.x), mish_f(av1.y + qa1.y));
            U32 a3 = pack_h2(mish_f(av1.x + qb1.x), mish_f(av1.y + qb1.y));
            *(uint4*)(Ab + (((ks*4 + mt)*32 + ln) << 4)) = make_uint4(a0,a1,a2,a3);
        }
    };

    float acc[2][8][4];
    #pragma unroll
    for (int mf = 0; mf < 2; mf++)
        #pragma unroll
        for (int nf = 0; nf < 8; nf++)
            #pragma unroll
            for (int u = 0; u < 4; u++) acc[mf][nf][u] = 0.0f;

    int nh = wn >> 1;                 // warp's nhalf
    int npb = (wn & 1) * 4;           // np base within nhalf section

    auto consume = [&](char* Ab, char* Bb){
        char* Bn = Bb + nh * 16384;
        #pragma unroll
        for (int ks = 0; ks < 4; ks++){
            uint4 aA = *(uint4*)(Ab + (((ks*4 + wm*2    )*32 + lane) << 4));
            uint4 aB = *(uint4*)(Ab + (((ks*4 + wm*2 + 1)*32 + lane) << 4));
            #pragma unroll
            for (int npp = 0; npp < 4; npp++){
                uint4 v = *(uint4*)(Bn + (((ks*8 + npb + npp)*32 + lane) << 4));
                MMA_F16(acc[0][2*npp    ], aA, v.x, v.y);
                MMA_F16(acc[1][2*npp    ], aB, v.x, v.y);
                MMA_F16(acc[0][2*npp + 1], aA, v.z, v.w);
                MMA_F16(acc[1][2*npp + 1], aB, v.z, v.w);
            }
        }
    };

    char* A0 = smc;          char* A1 = smc + 8192;
    char* A2 = smc + 16384;  char* A3 = smc + 24576;
    char* B0 = smc + 32768;  char* B1 = smc + 65536;
    U32 B0a = smem32 + 32768, B1a = smem32 + 65536;

    // phase 1: kick W{0,1}; av must be visible before produceA
    produceW(0, B0a);
    produceW(1, B1a);
    __syncthreads();                  // av/xi/b2 visible
    produceA(0, A0); produceA(1, A1); produceA(2, A2); produceA(3, A3);
    asm volatile("cp.async.wait_group 0;" ::: "memory");
    __syncthreads();                  // A + B{0,1} visible

    consume(A0, B0);
    __syncthreads();                  // B0 fully consumed by all warps
    produceW(2, B0a);                 // async refill B0 under consume(A1,B1)
    consume(A1, B1);
    asm volatile("cp.async.wait_group 0;" ::: "memory");
    __syncthreads();                  // B0 new visible; B1 consumed by all
    produceW(3, B1a);                 // async refill B1 under consume(A2,B0)
    consume(A2, B0);
    asm volatile("cp.async.wait_group 0;" ::: "memory");
    __syncthreads();                  // B1 new visible
    consume(A3, B1);

    // ---- epilogue: residual + bias; x_j via direct L2-hot LDG ----
    size_t rowbase = (size_t)ti * 64;
    const float* embB = emb + (size_t)(b*64) * 128;

    #pragma unroll
    for (int mf = 0; mf < 2; mf++){
        int jr0 = wm*32 + mf*16 + g;
        int jr1 = jr0 + 8;
        float* o0 = outp + (rowbase + jr0) * 256;
        float* o1 = outp + (rowbase + jr1) * 256;
        #pragma unroll
        for (int npp = 0; npp < 4; npp++){
            #pragma unroll
            for (int inner = 0; inner < 2; inner++){
                int nf = 2*npp + inner;
                int col = nh*128 + (npb + npp)*16 + inner*8 + 2*tl;
                float add00, add01, add10, add11;
                if (nh == 0){
                    float x0 = xi_s[col], x1 = xi_s[col + 1];
                    add00 = x0; add01 = x1; add10 = x0; add11 = x1;
                } else {
                    int cc = col - 128;
                    float2 va = __ldg((const float2*)(embB + (size_t)jr0*128 + cc));
                    float2 vb = __ldg((const float2*)(embB + (size_t)jr1*128 + cc));
                    add00 = va.x; add01 = va.y;
                    add10 = vb.x; add11 = vb.y;
                }
                float bb0 = b2_s[col], bb1 = b2_s[col + 1];
                float2 v0 = make_float2(acc[mf][nf][0] + add00 + bb0,
                                        acc[mf][nf][1] + add01 + bb1);
                float2 v1 = make_float2(acc[mf][nf][2] + add10 + bb0,
                                        acc[mf][nf][3] + add11 + bb1);
                *(float2*)&o0[col] = v0;
                *(float2*)&o1[col] = v1;
            }
        }
    }
}

// ---------------------------------------------------------------------------
extern "C" void kernel_launch(void* const* d_in, const int* in_sizes, int n_in,
                              void* d_out, int out_size)
{
    (void)in_sizes; (void)n_in; (void)out_size;
    const float* emb  = (const float*)d_in[0];
    const float* W1_0 = (const float*)d_in[2];
    const float* b1_0 = (const float*)d_in[3];
    const float* W2_0 = (const float*)d_in[4];
    const float* b2_0 = (const float*)d_in[5];
    const float* W1_1 = (const float*)d_in[6];
    const float* b1_1 = (const float*)d_in[7];
    const float* W2_1 = (const float*)d_in[8];
    const float* b2_1 = (const float*)d_in[9];
    const float* W1_2 = (const float*)d_in[10];
    const float* b1_2 = (const float*)d_in[11];
    const float* W2_2 = (const float*)d_in[12];
    const float* b2_2 = (const float*)d_in[13];
    const float* W1_3 = (const float*)d_in[14];
    const float* b1_3 = (const float*)d_in[15];
    const float* W2_3 = (const float*)d_in[16];
    const float* b2_3 = (const float*)d_in[17];
    float* out = (float*)d_out;

    static int smem_set = 0;
    if (!smem_set){
        cudaFuncSetAttribute(pair_mma_kernel,
                             cudaFuncAttributeMaxDynamicSharedMemorySize,
                             PAIR_SMEM_BYTES);
        cudaFuncSetAttribute(prep_kernel,
                             cudaFuncAttributeMaxDynamicSharedMemorySize,
                             PREP_SMEM_BYTES);
        smem_set = 1;
    }

    prep_kernel<<<1600, 256, PREP_SMEM_BYTES>>>(
        emb,
        W1_1, W1_2, W1_3,
        W2_1, W2_2, W2_3,
        W1_0, b1_0, W2_0, b2_0,
        out);
    pair_mma_kernel<<<dim3(2048, 3), 256, PAIR_SMEM_BYTES>>>(
        emb,
        b1_1, b1_2, b1_3,
        b2_1, b2_2, b2_3,
        out + 262144);
}

// round 15
// speedup vs baseline: 1.6184x; 1.0798x over previous
#include <cuda_runtime.h>

typedef unsigned int U32;
typedef unsigned short U16;

static __device__ __forceinline__ float mish_f(float x){
    // mish(x) = x * ((1+e^x)^2 - 1) / ((1+e^x)^2 + 1), division via
    // bit-hack reciprocal + 2 Newton iterations (FMA pipe, no MUFU.RCP).
    float e  = __expf(fminf(x, 30.0f));
    float u  = 1.0f + e;
    float u2 = u * u;
    float d  = u2 + 1.0f;
    float r  = __int_as_float(0x7EF311C2 - __float_as_int(d));
    r = r * (2.0f - d * r);
    r = r * (2.0f - d * r);
    return x * (u2 - 1.0f) * r;
}

// g_AB: [pred(3)][half(2)][row(2048)][col(256)]  (P = x@W1_top, Q = x@W1_bot)
__device__ float g_AB[6 * 2048 * 256];
// g_W2h: W2 in fp16, fragment order: [pred(3)][nhalf(2)][chunk(4)][8192 halves]
__device__ U16 g_W2h[3 * 65536];

static __device__ __forceinline__ U32 pack_h2(float lo, float hi){
    U32 r;
    asm("cvt.rn.f16x2.f32 %0, %1, %2;" : "=r"(r) : "f"(hi), "f"(lo));
    return r;
}

static __device__ __forceinline__ void cp16(U32 dst, const void* src){
    asm volatile("cp.async.cg.shared.global [%0], [%1], 16;"
                 :: "r"(dst), "l"(src) : "memory");
}

// ---------------------------------------------------------------------------
// prep bodies
// ---------------------------------------------------------------------------
static __device__ void w2frag_body(int blk,
    const float* __restrict__ W2a, const float* __restrict__ W2b,
    const float* __restrict__ W2c)
{
    int idx = blk * 256 + threadIdx.x;          // 0 .. 196607
    int p = idx >> 16;
    int rem = idx & 65535;
    int k = rem >> 8, n = rem & 255;
    const float* W2 = (p == 0) ? W2a : (p == 1) ? W2b : W2c;
    float v = W2[k * 256 + n];
    U16 hv;
    asm("{ .reg .f16 t; cvt.rn.f16.f32 t, %1; mov.b16 %0, t; }" : "=h"(hv) : "f"(v));
    int c = k >> 6, kk = k & 63;
    int ks = kk >> 4, r = kk & 15;
    int hi = r >> 3, r8 = r & 7, tl = r8 >> 1, comp = r8 & 1;
    int nhalf = n >> 7, nl = n & 127;
    int nt = nl >> 3, np = nt >> 1, odd = nt & 1, g = nl & 7;
    int lane = g * 4 + tl;
    int halfidx = ((ks * 8 + np) * 32 + lane) * 8 + (odd * 2 + hi) * 2 + comp;
    g_W2h[((p * 2 + nhalf) * 4 + c) * 8192 + halfidx] = hv;
}

// ab: full-tile single-sync version. Xs[128 k][65 pad] + Ws[128 k][64].
static __device__ void ab_body(float* sh,
    const float* __restrict__ emb,
    const float* __restrict__ W1a, const float* __restrict__ W1b,
    const float* __restrict__ W1c,
    int bx, int by, int z)
{
    float (*Xs)[65] = (float(*)[65])sh;
    float (*Ws)[64] = (float(*)[64])(sh + 128*65);
    int p = z >> 1, half = z & 1;
    const float* W = (p == 0 ? W1a : (p == 1 ? W1b : W1c)) + half * 128 * 256;
    int row0 = by * 64;
    int col0 = bx * 64;
    int tid = threadIdx.x;
    int tr = tid >> 4, tc = tid & 15;

    #pragma unroll
    for (int it = 0; it < 32; it++){
        int idx = tid + it*256;       // idx = r*128 + k
        int r = idx >> 7, k = idx & 127;
        Xs[k][r] = emb[(row0 + r)*128 + k];
    }
    #pragma unroll
    for (int it = 0; it < 32; it++){
        int idx = tid + it*256;       // idx = k*64 + c
        int k = idx >> 6, c = idx & 63;
        Ws[k][c] = W[k*256 + col0 + c];
    }
    __syncthreads();

    float acc[4][4];
    #pragma unroll
    for (int r = 0; r < 4; r++)
        #pragma unroll
        for (int c = 0; c < 4; c++) acc[r][c] = 0.0f;

    #pragma unroll 4
    for (int k = 0; k < 128; k++){
        float a[4], bv[4];
        #pragma unroll
        for (int r = 0; r < 4; r++) a[r] = Xs[k][tr*4 + r];
        #pragma unroll
        for (int c = 0; c < 4; c++) bv[c] = Ws[k][tc*4 + c];
        #pragma unroll
        for (int r = 0; r < 4; r++)
            #pragma unroll
            for (int c = 0; c < 4; c++)
                acc[r][c] = fmaf(a[r], bv[c], acc[r][c]);
    }

    float* out = g_AB + (size_t)z * 2048 * 256;
    #pragma unroll
    for (int r = 0; r < 4; r++){
        float4 v = make_float4(acc[r][0], acc[r][1], acc[r][2], acc[r][3]);
        *(float4*)&out[(row0 + tr*4 + r)*256 + col0 + tc*4] = v;
    }
}

static __device__ void p0_body(float* sh,
    const float* __restrict__ emb,
    const float* __restrict__ W1, const float* __restrict__ b1,
    const float* __restrict__ W2, const float* __restrict__ b2,
    float* __restrict__ out, int blk)
{
    float (*buf)[33] = (float(*)[33])sh;                 // 128 x 33
    float (*wch)[128] = (float(*)[128])(sh + 4224);      // 16 x 128
    float* bias = sh + 4224 + 2048;
    int row0 = blk * 32;
    int tid = threadIdx.x;
    int tr = tid >> 5, tc = tid & 31;

    for (int idx = tid; idx < 32*128; idx += 256){
        int k = idx & 127, r = idx >> 7;
        buf[k][r] = emb[(row0 + r)*128 + k];
    }
    if (tid < 128) bias[tid] = b1[tid];
    __syncthreads();

    float acc[4][4];
    #pragma unroll
    for (int r = 0; r < 4; r++)
        #pragma unroll
        for (int c = 0; c < 4; c++) acc[r][c] = 0.0f;

    for (int k0 = 0; k0 < 128; k0 += 16){
        #pragma unroll
        for (int pp = 0; pp < 8; pp++){
            int idx = tid + pp*256;
            int c = idx & 127, kk = idx >> 7;
            wch[kk][c] = W1[(k0 + kk)*128 + c];
        }
        __syncthreads();
        #pragma unroll
        for (int k = 0; k < 16; k++){
            float a[4], bv[4];
            #pragma unroll
            for (int r = 0; r < 4; r++) a[r] = buf[k0 + k][tr*4 + r];
            #pragma unroll
            for (int c = 0; c < 4; c++) bv[c] = wch[k][tc*4 + c];
            #pragma unroll
            for (int r = 0; r < 4; r++)
                #pragma unroll
                for (int c = 0; c < 4; c++)
                    acc[r][c] = fmaf(a[r], bv[c], acc[r][c]);
        }
        __syncthreads();
    }

    float hval[4][4];
    #pragma unroll
    for (int r = 0; r < 4; r++)
        #pragma unroll
        for (int c = 0; c < 4; c++)
            hval[r][c] = mish_f(acc[r][c] + bias[tc*4 + c]);
    __syncthreads();
    #pragma unroll
    for (int r = 0; r < 4; r++)
        #pragma unroll
        for (int c = 0; c < 4; c++)
            buf[tc*4 + c][tr*4 + r] = hval[r][c];
    if (tid < 128) bias[tid] = b2[tid];

    float acc2[4][4];
    #pragma unroll
    for (int r = 0; r < 4; r++)
        #pragma unroll
        for (int c = 0; c < 4; c++) acc2[r][c] = 0.0f;

    for (int k0 = 0; k0 < 128; k0 += 16){
        #pragma unroll
        for (int pp = 0; pp < 8; pp++){
            int idx = tid + pp*256;
            int c = idx & 127, kk = idx >> 7;
            wch[kk][c] = W2[(k0 + kk)*128 + c];
        }
        __syncthreads();
        #pragma unroll
        for (int k = 0; k < 16; k++){
            float a[4], bv[4];
            #pragma unroll
            for (int r = 0; r < 4; r++) a[r] = buf[k0 + k][tr*4 + r];
            #pragma unroll
            for (int c = 0; c < 4; c++) bv[c] = wch[k][tc*4 + c];
            #pragma unroll
            for (int r = 0; r < 4; r++)
                #pragma unroll
                for (int c = 0; c < 4; c++)
                    acc2[r][c] = fmaf(a[r], bv[c], acc2[r][c]);
        }
        __syncthreads();
    }

    #pragma unroll
    for (int r = 0; r < 4; r++){
        int row = row0 + tr*4 + r;
        float4 x = *(const float4*)&emb[row*128 + tc*4];
        float4 o = make_float4(x.x + acc2[r][0] + bias[tc*4+0],
                               x.y + acc2[r][1] + bias[tc*4+1],
                               x.z + acc2[r][2] + bias[tc*4+2],
                               x.w + acc2[r][3] + bias[tc*4+3]);
        *(float4*)&out[row*128 + tc*4] = o;
    }
}

// prep_kernel: blocks [0,768) = ab, [768,1536) = w2frag. (p0 rides in pair.)
#define PREP_SMEM_BYTES 66560
__global__ __launch_bounds__(256) void prep_kernel(
    const float* __restrict__ emb,
    const float* __restrict__ W1_1, const float* __restrict__ W1_2,
    const float* __restrict__ W1_3,
    const float* __restrict__ W2_1, const float* __restrict__ W2_2,
    const float* __restrict__ W2_3)
{
    extern __shared__ float sh[];
    int bz = blockIdx.x;
    if (bz < 768){
        ab_body(sh, emb, W1_1, W1_2, W1_3, bz & 3, (bz >> 2) & 31, bz >> 7);
    } else {
        w2frag_body(bz - 768, W2_1, W2_2, W2_3);
    }
}

// ---------------------------------------------------------------------------
// pair_mma_kernel: arity-2 via fp16 mma.sync (m16n8k16, f32 acc).
// Block = (pred p, ti). M=64 (j rows), N=256, K=256. Phase-form pipeline with
// overlapped B refills. Epilogue: raw accumulators staged through a 64x264
// smem tile, then ONE coalesced pass (LDS.128 + residual + bias + STG.128);
// kills the 8-wavefront/instr store scatter. Blocks x>=2048 (y==0) run p0.
// 256 threads, 8 warps (2M x 4N), warp tile 32x64, acc 64 regs.
// __launch_bounds__(256,2): 2 CTAs/SM.
// SMEM bytes: A0..A3 [0,32768) B0[32768,65536) B1[65536,98304)
//             av[98304,99328) xi[99328,99840) b2[99840,100864)
// Epilogue D tile: [64][264] floats at offset 0 (67584 B, fits A+B region).
// ---------------------------------------------------------------------------
#define PAIR_SMEM_BYTES 100864

#define MMA_F16(d, a, b0v, b1v) \
    asm volatile("mma.sync.aligned.m16n8k16.row.col.f32.f16.f16.f32 " \
        "{%0,%1,%2,%3}, {%4,%5,%6,%7}, {%8,%9}, {%0,%1,%2,%3};" \
        : "+f"(d[0]), "+f"(d[1]), "+f"(d[2]), "+f"(d[3]) \
        : "r"((a).x), "r"((a).y), "r"((a).z), "r"((a).w), \
          "r"(b0v), "r"(b1v))

__global__ __launch_bounds__(256, 2) void pair_mma_kernel(
    const float* __restrict__ emb,
    const float* __restrict__ b1a, const float* __restrict__ b1b, const float* __restrict__ b1c,
    const float* __restrict__ b2a, const float* __restrict__ b2b, const float* __restrict__ b2c,
    const float* __restrict__ W1_0, const float* __restrict__ b1_0,
    const float* __restrict__ W2_0, const float* __restrict__ b2_0,
    float* __restrict__ out)
{
    extern __shared__ char smc[];

    if (blockIdx.x >= 2048){
        if (blockIdx.y == 0)
            p0_body((float*)smc, emb, W1_0, b1_0, W2_0, b2_0, out,
                    blockIdx.x - 2048);
        return;
    }

    float* av   = (float*)(smc + 98304);
    float* xi_s = (float*)(smc + 99328);
    float* b2_s = (float*)(smc + 99840);
    U32 smem32;
    asm("{ .reg .u64 t; cvta.to.shared.u64 t, %1; cvt.u32.u64 %0, t; }"
        : "=r"(smem32) : "l"(smc));

    int p = blockIdx.y;
    const float* b1 = (p == 0) ? b1a : (p == 1) ? b1b : b1c;
    const float* b2 = (p == 0) ? b2a : (p == 1) ? b2b : b2c;
    float* outp = out + 262144 + (size_t)p * 33554432;

    int ti = blockIdx.x;              // 0..2047 = b*64 + i
    int b = ti >> 6;
    const float* Pi = g_AB + ((size_t)(p*2) * 2048 + (size_t)ti) * 256;
    const float* Q  = g_AB + ((size_t)(p*2 + 1) * 2048 + (size_t)(b*64)) * 256;
    const uint4* W0 = (const uint4*)g_W2h + (size_t)(p*2    ) * 4096;
    const uint4* W1 = (const uint4*)g_W2h + (size_t)(p*2 + 1) * 4096;

    int t = threadIdx.x;
    int wid = t >> 5, lane = t & 31;
    int wm = wid & 1, wn = wid >> 1;
    int g = lane >> 2, tl = lane & 3;

    // av[k] = P[i][k] + b1[k]; stage xi and full b2
    av[t] = Pi[t] + b1[t];
    if (t < 32){
        float4 v = ((const float4*)(emb + (size_t)ti * 128))[t];
        *(float4*)&xi_s[t*4] = v;
    } else if (t < 96){
        int t2 = t - 32;
        float4 bv = ((const float4*)b2)[t2];
        *(float4*)&b2_s[t2*4] = bv;
    }

    // W2 chunk async copy: both nhalf sections, 32KB total (8 uint4/thread)
    auto produceW = [&](int c, U32 Bs32){
        const uint4* s0 = W0 + c * 1024 + t;
        const uint4* s1 = W1 + c * 1024 + t;
        #pragma unroll
        for (int it = 0; it < 4; it++){
            cp16(Bs32 + (U32)(t + it*256) * 16u, s0 + it*256);
            cp16(Bs32 + 16384u + (U32)(t + it*256) * 16u, s1 + it*256);
        }
        asm volatile("cp.async.commit_group;" ::: "memory");
    };

    // A (h) fragments: 2 uint4 per thread per chunk, exact mma layout
    auto produceA = [&](int c, char* Ab){
        #pragma unroll
        for (int e = 0; e < 2; e++){
            int idx = t + e*256;
            int ks = idx >> 7;
            int mt = (idx >> 5) & 3;
            int ln = idx & 31;
            int gg = ln >> 2, tll = ln & 3;
            int j = mt*16 + gg;
            int kb = c*64 + ks*16 + 2*tll;
            const float* qr0 = Q + (size_t)j * 256 + kb;
            const float* qr1 = qr0 + 8 * 256;
            float2 qa0 = *(const float2*)qr0;
            float2 qa1 = *(const float2*)(qr0 + 8);
            float2 qb0 = *(const float2*)qr1;
            float2 qb1 = *(const float2*)(qr1 + 8);
            float2 av0 = *(const float2*)(av + kb);
            float2 av1 = *(const float2*)(av + kb + 8);
            U32 a0 = pack_h2(mish_f(av0.x + qa0.x), mish_f(av0.y + qa0.y));
            U32 a1 = pack_h2(mish_f(av0.x + qb0.x), mish_f(av0.y + qb0.y));
            U32 a2 = pack_h2(mish_f(av1.x + qa1.x), mish_f(av1.y + qa1.y));
            U32 a3 = pack_h2(mish_f(av1.x + qb1.x), mish_f(av1.y + qb1.y));
            *(uint4*)(Ab + (((ks*4 + mt)*32 + ln) << 4)) = make_uint4(a0,a1,a2,a3);
        }
    };

    float acc[2][8][4];
    #pragma unroll
    for (int mf = 0; mf < 2; mf++)
        #pragma unroll
        for (int nf = 0; nf < 8; nf++)
            #pragma unroll
            for (int u = 0; u < 4; u++) acc[mf][nf][u] = 0.0f;

    int nh = wn >> 1;                 // warp's nhalf
    int npb = (wn & 1) * 4;           // np base within nhalf section

    auto consume = [&](char* Ab, char* Bb){
        char* Bn = Bb + nh * 16384;
        #pragma unroll
        for (int ks = 0; ks < 4; ks++){
            uint4 aA = *(uint4*)(Ab + (((ks*4 + wm*2    )*32 + lane) << 4));
            uint4 aB = *(uint4*)(Ab + (((ks*4 + wm*2 + 1)*32 + lane) << 4));
            #pragma unroll
            for (int npp = 0; npp < 4; npp++){
                uint4 v = *(uint4*)(Bn + (((ks*8 + npb + npp)*32 + lane) << 4));
                MMA_F16(acc[0][2*npp    ], aA, v.x, v.y);
                MMA_F16(acc[1][2*npp    ], aB, v.x, v.y);
                MMA_F16(acc[0][2*npp + 1], aA, v.z, v.w);
                MMA_F16(acc[1][2*npp + 1], aB, v.z, v.w);
            }
        }
    };

    char* A0 = smc;          char* A1 = smc + 8192;
    char* A2 = smc + 16384;  char* A3 = smc + 24576;
    char* B0 = smc + 32768;  char* B1 = smc + 65536;
    U32 B0a = smem32 + 32768, B1a = smem32 + 65536;

    // phase 1: kick W{0,1}; av must be visible before produceA
    produceW(0, B0a);
    produceW(1, B1a);
    __syncthreads();                  // av/xi/b2 visible
    produceA(0, A0); produceA(1, A1); produceA(2, A2); produceA(3, A3);
    asm volatile("cp.async.wait_group 0;" ::: "memory");
    __syncthreads();                  // A + B{0,1} visible

    consume(A0, B0);
    __syncthreads();                  // B0 fully consumed by all warps
    produceW(2, B0a);                 // async refill B0 under consume(A1,B1)
    consume(A1, B1);
    asm volatile("cp.async.wait_group 0;" ::: "memory");
    __syncthreads();                  // B0 new visible; B1 consumed by all
    produceW(3, B1a);                 // async refill B1 under consume(A2,B0)
    consume(A2, B0);
    asm volatile("cp.async.wait_group 0;" ::: "memory");
    __syncthreads();                  // B1 new visible
    consume(A3, B1);

    // ---- epilogue: stage raw acc in smem, then one coalesced pass ----
    __syncthreads();                  // A/B regions dead
    float* D = (float*)smc;           // [64][264] floats
    #pragma unroll
    for (int mf = 0; mf < 2; mf++){
        int jr0 = wm*32 + mf*16 + g;
        int jr1 = jr0 + 8;
        #pragma unroll
        for (int npp = 0; npp < 4; npp++){
            #pragma unroll
            for (int inner = 0; inner < 2; inner++){
                int nf = 2*npp + inner;
                int col = nh*128 + (npb + npp)*16 + inner*8 + 2*tl;
                *(float2*)&D[jr0*264 + col] =
                    make_float2(acc[mf][nf][0], acc[mf][nf][1]);
                *(float2*)&D[jr1*264 + col] =
                    make_float2(acc[mf][nf][2], acc[mf][nf][3]);
            }
        }
    }
    __syncthreads();

    size_t rowbase = (size_t)ti * 64;
    const float* embB = emb + (size_t)(b*64) * 128;
    #pragma unroll
    for (int it = 0; it < 16; it++){
        int idx = t + it*256;
        int r = idx >> 6, c4 = idx & 63;
        int col = c4 * 4;
        float4 d = *(float4*)&D[r*264 + col];
        float4 xv;
        if (col < 128) xv = *(float4*)&xi_s[col];
        else xv = __ldg((const float4*)(embB + (size_t)r*128 + (col - 128)));
        float4 bb = *(float4*)&b2_s[col];
        float4 o = make_float4(d.x + xv.x + bb.x, d.y + xv.y + bb.y,
                               d.z + xv.z + bb.z, d.w + xv.w + bb.w);
        *(float4*)&outp[(rowbase + r)*256 + col] = o;
    }
}

// ---------------------------------------------------------------------------
extern "C" void kernel_launch(void* const* d_in, const int* in_sizes, int n_in,
                              void* d_out, int out_size)
{
    (void)in_sizes; (void)n_in; (void)out_size;
    const float* emb  = (const float*)d_in[0];
    const float* W1_0 = (const float*)d_in[2];
    const float* b1_0 = (const float*)d_in[3];
    const float* W2_0 = (const float*)d_in[4];
    const float* b2_0 = (const float*)d_in[5];
    const float* W1_1 = (const float*)d_in[6];
    const float* b1_1 = (const float*)d_in[7];
    const float* W2_1 = (const float*)d_in[8];
    const float* b2_1 = (const float*)d_in[9];
    const float* W1_2 = (const float*)d_in[10];
    const float* b1_2 = (const float*)d_in[11];
    const float* W2_2 = (const float*)d_in[12];
    const float* b2_2 = (const float*)d_in[13];
    const float* W1_3 = (const float*)d_in[14];
    const float* b1_3 = (const float*)d_in[15];
    const float* W2_3 = (const float*)d_in[16];
    const float* b2_3 = (const float*)d_in[17];
    float* out = (float*)d_out;

    static int smem_set = 0;
    if (!smem_set){
        cudaFuncSetAttribute(pair_mma_kernel,
                             cudaFuncAttributeMaxDynamicSharedMemorySize,
                             PAIR_SMEM_BYTES);
        cudaFuncSetAttribute(prep_kernel,
                             cudaFuncAttributeMaxDynamicSharedMemorySize,
                             PREP_SMEM_BYTES);
        smem_set = 1;
    }

    prep_kernel<<<1536, 256, PREP_SMEM_BYTES>>>(
        emb,
        W1_1, W1_2, W1_3,
        W2_1, W2_2, W2_3);
    pair_mma_kernel<<<dim3(2112, 3), 256, PAIR_SMEM_BYTES>>>(
        emb,
        b1_1, b1_2, b1_3,
        b2_1, b2_2, b2_3,
        W1_0, b1_0, W2_0, b2_0,
        out);
}